// round 4
// baseline (speedup 1.0000x reference)
#include <cuda_runtime.h>
#include <math.h>

#define L_SEQ   2048
#define N_EMBD  1024
#define D_INNER 2048
#define D_STATE 16
#define DT_RANK 64
#define D_CONV  4
#define XDBL    (DT_RANK + 2 * D_STATE)   /* 96 */
#define VOCAB   50257
#define N_LAYERS 4

/* ---------------- scratch (static device allocations, allowed) ------------ */
__device__ float g_x[L_SEQ * N_EMBD];
__device__ float g_h[L_SEQ * N_EMBD];
__device__ float g_xr[L_SEQ * 2 * D_INNER];
__device__ float g_xc[L_SEQ * D_INNER];
__device__ float g_xdbl[L_SEQ * XDBL];
__device__ float g_delta[L_SEQ * D_INNER];
__device__ float g_y[L_SEQ * D_INNER];

__device__ __forceinline__ float silu_f(float v) { return v / (1.f + __expf(-v)); }
__device__ __forceinline__ float softplus_f(float v) {
    if (v > 20.f) return v;
    return log1pf(__expf(v));
}

/* ---------------- embedding gather --------------------------------------- */
__global__ void embed_kernel(const int* __restrict__ tok,
                             const float* __restrict__ W,
                             float* __restrict__ x) {
    int row = blockIdx.x;
    int t = tok[row];
    const float4* src = (const float4*)(W + (size_t)t * N_EMBD);
    float4* dst = (float4*)(x + (size_t)row * N_EMBD);
    dst[threadIdx.x] = src[threadIdx.x];   /* 256 thr * 4 = 1024 */
}

/* ---------------- rmsnorm: one block per row ------------------------------ */
__global__ void rmsnorm_kernel(const float* __restrict__ x,
                               const float* __restrict__ w,
                               const float* __restrict__ b,
                               float* __restrict__ out) {
    int row = blockIdx.x;
    const float4* xv = (const float4*)(x + (size_t)row * N_EMBD);
    float4 v = xv[threadIdx.x];
    float ss = v.x * v.x + v.y * v.y + v.z * v.z + v.w * v.w;
#pragma unroll
    for (int o = 16; o; o >>= 1) ss += __shfl_xor_sync(0xffffffffu, ss, o);
    __shared__ float red[8];
    if ((threadIdx.x & 31) == 0) red[threadIdx.x >> 5] = ss;
    __syncthreads();
    float tot = 0.f;
#pragma unroll
    for (int i = 0; i < 8; i++) tot += red[i];
    float inv = rsqrtf(tot * (1.f / N_EMBD) + 1e-6f);
    const float4* wv = (const float4*)w;
    const float4* bv = (const float4*)b;
    float4 ww = wv[threadIdx.x], bb = bv[threadIdx.x];
    float4 o4;
    o4.x = v.x * inv * ww.x + bb.x;
    o4.y = v.y * inv * ww.y + bb.y;
    o4.z = v.z * inv * ww.z + bb.z;
    o4.w = v.w * inv * ww.w + bb.w;
    ((float4*)(out + (size_t)row * N_EMBD))[threadIdx.x] = o4;
}

/* ---------------- depthwise causal conv (width 4) + silu ----------------- */
__global__ void conv_silu_kernel(const float* __restrict__ xr,   /* [L, 2*D_INNER], use first half */
                                 const float* __restrict__ cw,   /* [D_INNER, 4] for this layer */
                                 const float* __restrict__ cb,   /* [D_INNER] */
                                 float* __restrict__ xc) {       /* [L, D_INNER] */
    int idx = blockIdx.x * blockDim.x + threadIdx.x;
    int t = idx >> 11;
    int d = idx & (D_INNER - 1);
    const float* w = cw + d * 4;
    float acc = cb[d];
#pragma unroll
    for (int j = 0; j < 4; j++) {
        int ti = t - 3 + j;
        float xv = (ti >= 0) ? xr[(size_t)ti * (2 * D_INNER) + d] : 0.f;
        acc += xv * w[j];
    }
    xc[idx] = silu_f(acc);
}

/* ---------------- selective scan: 16 lanes per channel -------------------- */
/* block = 128 threads = 8 channels; grid = 256 blocks                        */
__global__ void scan_kernel(const float* __restrict__ xdbl,   /* [L, 96]: [.,64:80]=B [.,80:96]=C */
                            const float* __restrict__ delta,  /* [L, D_INNER] */
                            const float* __restrict__ xc,     /* [L, D_INNER] (u) */
                            const float* __restrict__ xr,     /* [L, 2*D_INNER] (res = 2nd half) */
                            const float* __restrict__ A_log,  /* [D_INNER, 16] this layer */
                            const float* __restrict__ Dp,     /* [D_INNER] */
                            float* __restrict__ y) {          /* [L, D_INNER] */
    int lane = threadIdx.x & 15;
    int ch = blockIdx.x * (blockDim.x >> 4) + (threadIdx.x >> 4);
    float Aval = -__expf(A_log[ch * D_STATE + lane]);
    float Dv = Dp[ch];
    float s = 0.f;
    for (int t = 0; t < L_SEQ; t++) {
        float dt = delta[(size_t)t * D_INNER + ch];
        float ut = xc[(size_t)t * D_INNER + ch];
        float Bt = xdbl[(size_t)t * XDBL + DT_RANK + lane];
        float Ct = xdbl[(size_t)t * XDBL + DT_RANK + D_STATE + lane];
        s = __expf(dt * Aval) * s + (dt * Bt) * ut;
        float v = s * Ct;
        v += __shfl_xor_sync(0xffffffffu, v, 8);
        v += __shfl_xor_sync(0xffffffffu, v, 4);
        v += __shfl_xor_sync(0xffffffffu, v, 2);
        v += __shfl_xor_sync(0xffffffffu, v, 1);
        if (lane == 0) {
            float r = xr[(size_t)t * (2 * D_INNER) + D_INNER + ch];
            y[(size_t)t * D_INNER + ch] = (v + ut * Dv) * silu_f(r);
        }
    }
}

/* ---------------- NT SGEMM: C[m,n] = sum_k A[m,k] * B[n,k] ---------------- */
/* 64x64 tile, BK=16, 256 threads, 4x4 per thread.                            */
/* mode 0: C = acc ; mode 1: C += acc ; mode 2: C = softplus(acc + bias[n])   */
#define BM 64
#define BN 64
#define BK 16
__global__ void __launch_bounds__(256)
sgemm_nt(const float* __restrict__ A, int lda,
         const float* __restrict__ B, int ldb,
         float* __restrict__ C, int ldc,
         int N, int K, int mode, const float* __restrict__ bias) {
    __shared__ float As[BK][BM];
    __shared__ float Bs[BK][BN];
    int tid = threadIdx.x;
    int m0 = blockIdx.y * BM;
    int n0 = blockIdx.x * BN;
    int lr = tid >> 2;             /* 0..63: row within tile */
    int lc = (tid & 3) * 4;        /* 0,4,8,12: col (float4) within BK */
    int ty = tid >> 4;             /* 0..15 */
    int tx = tid & 15;             /* 0..15 */

    float acc[4][4];
#pragma unroll
    for (int i = 0; i < 4; i++)
#pragma unroll
        for (int j = 0; j < 4; j++) acc[i][j] = 0.f;

    for (int k0 = 0; k0 < K; k0 += BK) {
        float4 av = *(const float4*)(A + (size_t)(m0 + lr) * lda + k0 + lc);
        As[lc + 0][lr] = av.x; As[lc + 1][lr] = av.y;
        As[lc + 2][lr] = av.z; As[lc + 3][lr] = av.w;
        int bn = n0 + lr;
        float4 bv = make_float4(0.f, 0.f, 0.f, 0.f);
        if (bn < N) bv = *(const float4*)(B + (size_t)bn * ldb + k0 + lc);
        Bs[lc + 0][lr] = bv.x; Bs[lc + 1][lr] = bv.y;
        Bs[lc + 2][lr] = bv.z; Bs[lc + 3][lr] = bv.w;
        __syncthreads();
#pragma unroll
        for (int k = 0; k < BK; k++) {
            float4 af = *(const float4*)&As[k][ty * 4];
            float4 bf = *(const float4*)&Bs[k][tx * 4];
            float a_[4] = {af.x, af.y, af.z, af.w};
            float b_[4] = {bf.x, bf.y, bf.z, bf.w};
#pragma unroll
            for (int i = 0; i < 4; i++)
#pragma unroll
                for (int j = 0; j < 4; j++) acc[i][j] += a_[i] * b_[j];
        }
        __syncthreads();
    }

#pragma unroll
    for (int i = 0; i < 4; i++) {
        int m = m0 + ty * 4 + i;
#pragma unroll
        for (int j = 0; j < 4; j++) {
            int n = n0 + tx * 4 + j;
            if (n < N) {
                float v = acc[i][j];
                if (mode == 1) v += C[(size_t)m * ldc + n];
                else if (mode == 2) v = softplus_f(v + bias[n]);
                C[(size_t)m * ldc + n] = v;
            }
        }
    }
}

/* ---------------- launcher ------------------------------------------------ */
extern "C" void kernel_launch(void* const* d_in, const int* in_sizes, int n_in,
                              void* d_out, int out_size) {
    const int*   tokens   = (const int*)  d_in[0];
    const float* emb_W    = (const float*)d_in[1];
    const float* in_projW = (const float*)d_in[2];
    const float* conv_W   = (const float*)d_in[3];
    const float* conv_b   = (const float*)d_in[4];
    const float* xproj_W  = (const float*)d_in[5];
    const float* dt_W     = (const float*)d_in[6];
    const float* dt_b     = (const float*)d_in[7];
    const float* A_log    = (const float*)d_in[8];
    const float* Dp       = (const float*)d_in[9];
    const float* out_W    = (const float*)d_in[10];
    const float* rms_w    = (const float*)d_in[11];
    const float* rms_b    = (const float*)d_in[12];
    const float* normf_w  = (const float*)d_in[13];
    const float* normf_b  = (const float*)d_in[14];
    float* out = (float*)d_out;

    float *x, *h, *xr, *xc, *xdbl, *delta, *y;
    cudaGetSymbolAddress((void**)&x,     g_x);
    cudaGetSymbolAddress((void**)&h,     g_h);
    cudaGetSymbolAddress((void**)&xr,    g_xr);
    cudaGetSymbolAddress((void**)&xc,    g_xc);
    cudaGetSymbolAddress((void**)&xdbl,  g_xdbl);
    cudaGetSymbolAddress((void**)&delta, g_delta);
    cudaGetSymbolAddress((void**)&y,     g_y);

    embed_kernel<<<L_SEQ, 256>>>(tokens, emb_W, x);

    for (int i = 0; i < N_LAYERS; i++) {
        /* h = rmsnorm(x) */
        rmsnorm_kernel<<<L_SEQ, 256>>>(x, rms_w + i * N_EMBD, rms_b + i * N_EMBD, h);
        /* xr = h @ in_proj_W^T   [2048, 4096] */
        sgemm_nt<<<dim3(2 * D_INNER / BN, L_SEQ / BM), 256>>>(
            h, N_EMBD, in_projW + (size_t)i * 2 * D_INNER * N_EMBD, N_EMBD,
            xr, 2 * D_INNER, 2 * D_INNER, N_EMBD, 0, nullptr);
        /* xc = silu(depthwise causal conv(xr[:, :d_inner])) */
        conv_silu_kernel<<<L_SEQ * D_INNER / 256, 256>>>(
            xr, conv_W + (size_t)i * D_INNER * D_CONV, conv_b + i * D_INNER, xc);
        /* x_dbl = xc @ xproj_W^T   [2048, 96] */
        sgemm_nt<<<dim3((XDBL + BN - 1) / BN, L_SEQ / BM), 256>>>(
            xc, D_INNER, xproj_W + (size_t)i * XDBL * D_INNER, D_INNER,
            xdbl, XDBL, XDBL, D_INNER, 0, nullptr);
        /* delta = softplus(x_dbl[:, :64] @ dt_W^T + dt_b)   [2048, 2048] */
        sgemm_nt<<<dim3(D_INNER / BN, L_SEQ / BM), 256>>>(
            xdbl, XDBL, dt_W + (size_t)i * D_INNER * DT_RANK, DT_RANK,
            delta, D_INNER, D_INNER, DT_RANK, 2, dt_b + i * D_INNER);
        /* y = selective_scan(...) * silu(res), fused epilogue */
        scan_kernel<<<D_INNER / 8, 128>>>(
            xdbl, delta, xc, xr,
            A_log + (size_t)i * D_INNER * D_STATE, Dp + i * D_INNER, y);
        /* x += y @ out_W^T   [2048, 1024] */
        sgemm_nt<<<dim3(N_EMBD / BN, L_SEQ / BM), 256>>>(
            y, D_INNER, out_W + (size_t)i * N_EMBD * D_INNER, D_INNER,
            x, N_EMBD, N_EMBD, D_INNER, 1, nullptr);
    }

    /* final norm + tied LM head: out = rmsnorm(x) @ emb_W^T   [2048, 50257] */
    rmsnorm_kernel<<<L_SEQ, 256>>>(x, normf_w, normf_b, h);
    sgemm_nt<<<dim3((VOCAB + BN - 1) / BN, L_SEQ / BM), 256>>>(
        h, N_EMBD, emb_W, N_EMBD, out, VOCAB, VOCAB, N_EMBD, 0, nullptr);
}

// round 9
// speedup vs baseline: 1.0867x; 1.0867x over previous
#include <cuda_runtime.h>
#include <math.h>
#include <stdint.h>

#define L_SEQ   2048
#define N_EMBD  1024
#define D_INNER 2048
#define D_STATE 16
#define DT_RANK 64
#define D_CONV  4
#define XDBL    (DT_RANK + 2 * D_STATE)   /* 96 */
#define VOCAB   50257
#define N_LAYERS 4

/* ---------------- scratch (static device allocations, allowed) ------------ */
__device__ float g_x[L_SEQ * N_EMBD];
__device__ float g_h[L_SEQ * N_EMBD];
__device__ float g_xr[L_SEQ * 2 * D_INNER];
__device__ float g_xc[L_SEQ * D_INNER];
__device__ float g_xdbl[L_SEQ * XDBL];
__device__ float g_delta[L_SEQ * D_INNER];
__device__ float g_y[L_SEQ * D_INNER];

__device__ __forceinline__ float silu_f(float v) { return v / (1.f + __expf(-v)); }
__device__ __forceinline__ float softplus_f(float v) {
    if (v > 20.f) return v;
    return log1pf(__expf(v));
}
__device__ __forceinline__ uint32_t f2tf32(float f) {
    uint32_t r;
    asm("cvt.rna.tf32.f32 %0, %1;" : "=r"(r) : "f"(f));
    return r;
}
/* split fp32 into tf32 hi + tf32 lo (3xTF32 scheme) */
__device__ __forceinline__ void tf32split(uint32_t raw, uint32_t& hi, uint32_t& lo) {
    float f = __uint_as_float(raw);
    uint32_t h = f2tf32(f);
    float r = f - __uint_as_float(h);   /* exact */
    hi = h;
    lo = f2tf32(r);
}

#define MMA_TF32(acc, a0, a1, a2, a3, b0, b1)                                  \
    asm volatile(                                                              \
        "mma.sync.aligned.m16n8k8.row.col.f32.tf32.tf32.f32 "                  \
        "{%0,%1,%2,%3}, {%4,%5,%6,%7}, {%8,%9}, {%0,%1,%2,%3};"                \
        : "+f"(acc[0]), "+f"(acc[1]), "+f"(acc[2]), "+f"(acc[3])               \
        : "r"(a0), "r"(a1), "r"(a2), "r"(a3), "r"(b0), "r"(b1))

/* ========= 3xTF32 mma.sync NT GEMM: C[m,n] = sum_k A[m,k]B[n,k] =========== */
/* CTA 128x128, BK=32, 256 thr = 8 warps, warp tile 64x32 (m16n8k8 grid 4x4). */
/* SMEM holds raw fp32 bits [128][36]; hi/lo tf32 split at fragment load.     */
/* mode 0: C = acc ; mode 1: C += acc ; mode 2: C = softplus(acc + bias[n])   */
#define BKP 36
#define TILE_U32 (128 * BKP)              /* 4608 u32 = 18432 B */

__global__ void __launch_bounds__(256)
tmma_nt(const float* __restrict__ A, int lda,
        const float* __restrict__ B, int ldb,
        float* __restrict__ C, int ldc,
        int N, int K, int mode, const float* __restrict__ bias) {
    extern __shared__ uint32_t smem[];
    uint32_t* Abuf[2] = { smem,                smem + 2 * TILE_U32 };
    uint32_t* Bbuf[2] = { smem + TILE_U32,     smem + 3 * TILE_U32 };

    const int tid = threadIdx.x;
    const int wid = tid >> 5;
    const int lane = tid & 31;
    const int g = lane >> 2;               /* groupID 0..7 */
    const int t = lane & 3;                /* threadID_in_group */
    const int m0 = blockIdx.y * 128;
    const int n0 = blockIdx.x * 128;
    const int wm = (wid & 1) * 64;         /* warp M offset  */
    const int wn = (wid >> 1) * 32;        /* warp N offset  */

    /* loader mapping: row = tid/2, col base = (tid&1)*16 */
    const int lrow = tid >> 1;
    const int lcol = (tid & 1) * 16;
    const float* aptr = A + (size_t)(m0 + lrow) * lda + lcol;
    const int brow_g = n0 + lrow;
    const float* bptr = B + (size_t)brow_g * ldb + lcol;
    const bool bvalid = (brow_g < N);
    const uint32_t soff = (uint32_t)lrow * BKP + lcol;

    float acc[4][4][4];
#pragma unroll
    for (int mi = 0; mi < 4; mi++)
#pragma unroll
        for (int ni = 0; ni < 4; ni++)
#pragma unroll
            for (int q = 0; q < 4; q++) acc[mi][ni][q] = 0.f;

    const int nk = K >> 5;

    /* preload tile 0 (raw fp32 bits into SMEM) */
    float4 ar[4], br[4];
#pragma unroll
    for (int f = 0; f < 4; f++) {
        ar[f] = *(const float4*)(aptr + f * 4);
        br[f] = bvalid ? *(const float4*)(bptr + f * 4)
                       : make_float4(0.f, 0.f, 0.f, 0.f);
    }
    {
        float* As = (float*)Abuf[0];
        float* Bs = (float*)Bbuf[0];
#pragma unroll
        for (int f = 0; f < 4; f++) {
            As[soff + f * 4 + 0] = ar[f].x; As[soff + f * 4 + 1] = ar[f].y;
            As[soff + f * 4 + 2] = ar[f].z; As[soff + f * 4 + 3] = ar[f].w;
            Bs[soff + f * 4 + 0] = br[f].x; Bs[soff + f * 4 + 1] = br[f].y;
            Bs[soff + f * 4 + 2] = br[f].z; Bs[soff + f * 4 + 3] = br[f].w;
        }
    }
    __syncthreads();

    for (int kt = 0; kt < nk; kt++) {
        const int cur = kt & 1;
        /* prefetch next k-tile into registers (overlaps with MMA below) */
        if (kt + 1 < nk) {
            const float* ap = aptr + (kt + 1) * 32;
            const float* bp = bptr + (kt + 1) * 32;
#pragma unroll
            for (int f = 0; f < 4; f++) {
                ar[f] = *(const float4*)(ap + f * 4);
                br[f] = bvalid ? *(const float4*)(bp + f * 4)
                               : make_float4(0.f, 0.f, 0.f, 0.f);
            }
        }

        const uint32_t* As = Abuf[cur];
        const uint32_t* Bs = Bbuf[cur];
#pragma unroll
        for (int ks = 0; ks < 4; ks++) {
            const int k8 = ks * 8;
            uint32_t ah[4][4], al[4][4], bh[4][2], bl[4][2];
#pragma unroll
            for (int mi = 0; mi < 4; mi++) {
                const int r = wm + mi * 16 + g;
                tf32split(As[r * BKP + k8 + t],           ah[mi][0], al[mi][0]);
                tf32split(As[(r + 8) * BKP + k8 + t],     ah[mi][1], al[mi][1]);
                tf32split(As[r * BKP + k8 + t + 4],       ah[mi][2], al[mi][2]);
                tf32split(As[(r + 8) * BKP + k8 + t + 4], ah[mi][3], al[mi][3]);
            }
#pragma unroll
            for (int ni = 0; ni < 4; ni++) {
                const int n = wn + ni * 8 + g;
                tf32split(Bs[n * BKP + k8 + t],     bh[ni][0], bl[ni][0]);
                tf32split(Bs[n * BKP + k8 + t + 4], bh[ni][1], bl[ni][1]);
            }
#pragma unroll
            for (int mi = 0; mi < 4; mi++)
#pragma unroll
                for (int ni = 0; ni < 4; ni++) {
                    float* a4 = acc[mi][ni];
                    MMA_TF32(a4, ah[mi][0], ah[mi][1], ah[mi][2], ah[mi][3],
                             bl[ni][0], bl[ni][1]);
                    MMA_TF32(a4, al[mi][0], al[mi][1], al[mi][2], al[mi][3],
                             bh[ni][0], bh[ni][1]);
                    MMA_TF32(a4, ah[mi][0], ah[mi][1], ah[mi][2], ah[mi][3],
                             bh[ni][0], bh[ni][1]);
                }
        }

        /* stage next tile into the other buffer */
        if (kt + 1 < nk) {
            float* An = (float*)Abuf[cur ^ 1];
            float* Bn = (float*)Bbuf[cur ^ 1];
#pragma unroll
            for (int f = 0; f < 4; f++) {
                An[soff + f * 4 + 0] = ar[f].x; An[soff + f * 4 + 1] = ar[f].y;
                An[soff + f * 4 + 2] = ar[f].z; An[soff + f * 4 + 3] = ar[f].w;
                Bn[soff + f * 4 + 0] = br[f].x; Bn[soff + f * 4 + 1] = br[f].y;
                Bn[soff + f * 4 + 2] = br[f].z; Bn[soff + f * 4 + 3] = br[f].w;
            }
            __syncthreads();
        }
    }

    /* ---- epilogue: c0,c1 at (row g, cols 2t,2t+1); c2,c3 at row g+8 ------ */
    /* float2 only when (m*ldc + n) is even: ldc may be ODD (VOCAB=50257).    */
#pragma unroll
    for (int mi = 0; mi < 4; mi++) {
#pragma unroll
        for (int ni = 0; ni < 4; ni++) {
            const int m = m0 + wm + mi * 16 + g;
            const int n = n0 + wn + ni * 8 + t * 2;
            if (n < N) {
                float v0x = acc[mi][ni][0], v0y = acc[mi][ni][1];
                float v1x = acc[mi][ni][2], v1y = acc[mi][ni][3];
                float* p0 = C + (size_t)m * ldc + n;
                float* p1 = C + (size_t)(m + 8) * ldc + n;
                const bool al2 = ((((size_t)m * (size_t)ldc + (size_t)n) & 1) == 0);
                if (n + 1 < N) {
                    if (al2) {
                        float2 v0 = make_float2(v0x, v0y);
                        float2 v1 = make_float2(v1x, v1y);
                        if (mode == 1) {
                            float2 o0 = *(float2*)p0, o1 = *(float2*)p1;
                            v0.x += o0.x; v0.y += o0.y; v1.x += o1.x; v1.y += o1.y;
                        } else if (mode == 2) {
                            float b0 = bias[n], b1 = bias[n + 1];
                            v0.x = softplus_f(v0.x + b0); v0.y = softplus_f(v0.y + b1);
                            v1.x = softplus_f(v1.x + b0); v1.y = softplus_f(v1.y + b1);
                        }
                        *(float2*)p0 = v0;
                        *(float2*)p1 = v1;
                    } else {
                        if (mode == 1) {
                            v0x += p0[0]; v0y += p0[1];
                            v1x += p1[0]; v1y += p1[1];
                        } else if (mode == 2) {
                            float b0 = bias[n], b1 = bias[n + 1];
                            v0x = softplus_f(v0x + b0); v0y = softplus_f(v0y + b1);
                            v1x = softplus_f(v1x + b0); v1y = softplus_f(v1y + b1);
                        }
                        p0[0] = v0x; p0[1] = v0y;
                        p1[0] = v1x; p1[1] = v1y;
                    }
                } else {
                    if (mode == 1) { v0x += *p0; v1x += *p1; }
                    else if (mode == 2) {
                        float b0 = bias[n];
                        v0x = softplus_f(v0x + b0); v1x = softplus_f(v1x + b0);
                    }
                    *p0 = v0x;
                    *p1 = v1x;
                }
            }
        }
    }
}

/* ---------------- embedding gather --------------------------------------- */
__global__ void embed_kernel(const int* __restrict__ tok,
                             const float* __restrict__ W,
                             float* __restrict__ x) {
    int row = blockIdx.x;
    int t = tok[row];
    const float4* src = (const float4*)(W + (size_t)t * N_EMBD);
    float4* dst = (float4*)(x + (size_t)row * N_EMBD);
    dst[threadIdx.x] = src[threadIdx.x];
}

/* ---------------- rmsnorm: one block per row ------------------------------ */
__global__ void rmsnorm_kernel(const float* __restrict__ x,
                               const float* __restrict__ w,
                               const float* __restrict__ b,
                               float* __restrict__ out) {
    int row = blockIdx.x;
    const float4* xv = (const float4*)(x + (size_t)row * N_EMBD);
    float4 v = xv[threadIdx.x];
    float ss = v.x * v.x + v.y * v.y + v.z * v.z + v.w * v.w;
#pragma unroll
    for (int o = 16; o; o >>= 1) ss += __shfl_xor_sync(0xffffffffu, ss, o);
    __shared__ float red[8];
    if ((threadIdx.x & 31) == 0) red[threadIdx.x >> 5] = ss;
    __syncthreads();
    float tot = 0.f;
#pragma unroll
    for (int i = 0; i < 8; i++) tot += red[i];
    float inv = rsqrtf(tot * (1.f / N_EMBD) + 1e-6f);
    const float4* wv = (const float4*)w;
    const float4* bv = (const float4*)b;
    float4 ww = wv[threadIdx.x], bb = bv[threadIdx.x];
    float4 o4;
    o4.x = v.x * inv * ww.x + bb.x;
    o4.y = v.y * inv * ww.y + bb.y;
    o4.z = v.z * inv * ww.z + bb.z;
    o4.w = v.w * inv * ww.w + bb.w;
    ((float4*)(out + (size_t)row * N_EMBD))[threadIdx.x] = o4;
}

/* ---------------- depthwise causal conv (width 4) + silu ----------------- */
__global__ void conv_silu_kernel(const float* __restrict__ xr,
                                 const float* __restrict__ cw,
                                 const float* __restrict__ cb,
                                 float* __restrict__ xc) {
    int idx = blockIdx.x * blockDim.x + threadIdx.x;
    int t = idx >> 11;
    int d = idx & (D_INNER - 1);
    const float* w = cw + d * 4;
    float acc = cb[d];
#pragma unroll
    for (int j = 0; j < 4; j++) {
        int ti = t - 3 + j;
        float xv = (ti >= 0) ? xr[(size_t)ti * (2 * D_INNER) + d] : 0.f;
        acc += xv * w[j];
    }
    xc[idx] = silu_f(acc);
}

/* ---------------- selective scan: 16 lanes per channel -------------------- */
__global__ void scan_kernel(const float* __restrict__ xdbl,
                            const float* __restrict__ delta,
                            const float* __restrict__ xc,
                            const float* __restrict__ xr,
                            const float* __restrict__ A_log,
                            const float* __restrict__ Dp,
                            float* __restrict__ y) {
    int lane = threadIdx.x & 15;
    int ch = blockIdx.x * (blockDim.x >> 4) + (threadIdx.x >> 4);
    float Aval = -__expf(A_log[ch * D_STATE + lane]);
    float Dv = Dp[ch];
    float s = 0.f;
    for (int t = 0; t < L_SEQ; t++) {
        float dt = delta[(size_t)t * D_INNER + ch];
        float ut = xc[(size_t)t * D_INNER + ch];
        float Bt = xdbl[(size_t)t * XDBL + DT_RANK + lane];
        float Ct = xdbl[(size_t)t * XDBL + DT_RANK + D_STATE + lane];
        s = __expf(dt * Aval) * s + (dt * Bt) * ut;
        float v = s * Ct;
        v += __shfl_xor_sync(0xffffffffu, v, 8);
        v += __shfl_xor_sync(0xffffffffu, v, 4);
        v += __shfl_xor_sync(0xffffffffu, v, 2);
        v += __shfl_xor_sync(0xffffffffu, v, 1);
        if (lane == 0) {
            float r = xr[(size_t)t * (2 * D_INNER) + D_INNER + ch];
            y[(size_t)t * D_INNER + ch] = (v + ut * Dv) * silu_f(r);
        }
    }
}

/* ---------------- launcher ------------------------------------------------ */
#define TMMA_SMEM (4 * TILE_U32 * 4)   /* 73728 bytes */

static void launch_tmma(const float* A, int lda, const float* B, int ldb,
                        float* C, int ldc, int N, int K, int mode,
                        const float* bias) {
    dim3 grid((N + 127) / 128, L_SEQ / 128);
    tmma_nt<<<grid, 256, TMMA_SMEM>>>(A, lda, B, ldb, C, ldc, N, K, mode, bias);
}

extern "C" void kernel_launch(void* const* d_in, const int* in_sizes, int n_in,
                              void* d_out, int out_size) {
    const int*   tokens   = (const int*)  d_in[0];
    const float* emb_W    = (const float*)d_in[1];
    const float* in_projW = (const float*)d_in[2];
    const float* conv_W   = (const float*)d_in[3];
    const float* conv_b   = (const float*)d_in[4];
    const float* xproj_W  = (const float*)d_in[5];
    const float* dt_W     = (const float*)d_in[6];
    const float* dt_b     = (const float*)d_in[7];
    const float* A_log    = (const float*)d_in[8];
    const float* Dp       = (const float*)d_in[9];
    const float* out_W    = (const float*)d_in[10];
    const float* rms_w    = (const float*)d_in[11];
    const float* rms_b    = (const float*)d_in[12];
    const float* normf_w  = (const float*)d_in[13];
    const float* normf_b  = (const float*)d_in[14];
    float* out = (float*)d_out;

    cudaFuncSetAttribute(tmma_nt, cudaFuncAttributeMaxDynamicSharedMemorySize,
                         TMMA_SMEM);

    float *x, *h, *xr, *xc, *xdbl, *delta, *y;
    cudaGetSymbolAddress((void**)&x,     g_x);
    cudaGetSymbolAddress((void**)&h,     g_h);
    cudaGetSymbolAddress((void**)&xr,    g_xr);
    cudaGetSymbolAddress((void**)&xc,    g_xc);
    cudaGetSymbolAddress((void**)&xdbl,  g_xdbl);
    cudaGetSymbolAddress((void**)&delta, g_delta);
    cudaGetSymbolAddress((void**)&y,     g_y);

    embed_kernel<<<L_SEQ, 256>>>(tokens, emb_W, x);

    for (int i = 0; i < N_LAYERS; i++) {
        rmsnorm_kernel<<<L_SEQ, 256>>>(x, rms_w + i * N_EMBD, rms_b + i * N_EMBD, h);
        /* xr = h @ in_proj_W^T   [2048 x 4096 x 1024] */
        launch_tmma(h, N_EMBD, in_projW + (size_t)i * 2 * D_INNER * N_EMBD, N_EMBD,
                    xr, 2 * D_INNER, 2 * D_INNER, N_EMBD, 0, nullptr);
        conv_silu_kernel<<<L_SEQ * D_INNER / 256, 256>>>(
            xr, conv_W + (size_t)i * D_INNER * D_CONV, conv_b + i * D_INNER, xc);
        /* x_dbl = xc @ xproj_W^T   [2048 x 96 x 2048] */
        launch_tmma(xc, D_INNER, xproj_W + (size_t)i * XDBL * D_INNER, D_INNER,
                    xdbl, XDBL, XDBL, D_INNER, 0, nullptr);
        /* delta = softplus(x_dbl[:, :64] @ dt_W^T + dt_b)   [2048 x 2048 x 64] */
        launch_tmma(xdbl, XDBL, dt_W + (size_t)i * D_INNER * DT_RANK, DT_RANK,
                    delta, D_INNER, D_INNER, DT_RANK, 2, dt_b + i * D_INNER);
        scan_kernel<<<D_INNER / 8, 128>>>(
            xdbl, delta, xc, xr,
            A_log + (size_t)i * D_INNER * D_STATE, Dp + i * D_INNER, y);
        /* x += y @ out_W^T   [2048 x 1024 x 2048] */
        launch_tmma(y, D_INNER, out_W + (size_t)i * N_EMBD * D_INNER, D_INNER,
                    x, N_EMBD, N_EMBD, D_INNER, 1, nullptr);
    }

    rmsnorm_kernel<<<L_SEQ, 256>>>(x, normf_w, normf_b, h);
    /* tied LM head: out = h @ emb_W^T   [2048 x 50257 x 1024] */
    launch_tmma(h, N_EMBD, emb_W, N_EMBD, out, VOCAB, VOCAB, N_EMBD, 0, nullptr);
}

// round 10
// speedup vs baseline: 1.2013x; 1.1054x over previous
#include <cuda_runtime.h>
#include <math.h>
#include <stdint.h>

#define L_SEQ   2048
#define N_EMBD  1024
#define D_INNER 2048
#define D_STATE 16
#define DT_RANK 64
#define D_CONV  4
#define XDBL    (DT_RANK + 2 * D_STATE)   /* 96 */
#define VOCAB   50257
#define N_LAYERS 4

/* ---------------- scratch (static device allocations, allowed) ------------ */
__device__ float g_x[L_SEQ * N_EMBD];
__device__ float g_h[L_SEQ * N_EMBD];
__device__ float g_xr[L_SEQ * 2 * D_INNER];
__device__ float g_xc[L_SEQ * D_INNER];
__device__ float g_xdbl[L_SEQ * XDBL];
__device__ float g_delta[L_SEQ * D_INNER];
__device__ float g_y[L_SEQ * D_INNER];

__device__ __forceinline__ float silu_f(float v) { return v / (1.f + __expf(-v)); }
__device__ __forceinline__ float softplus_f(float v) {
    if (v > 20.f) return v;
    return log1pf(__expf(v));
}
__device__ __forceinline__ uint32_t f2tf32(float f) {
    uint32_t r;
    asm("cvt.rna.tf32.f32 %0, %1;" : "=r"(r) : "f"(f));
    return r;
}
/* split fp32 into tf32 hi + tf32 lo (3xTF32 scheme) */
__device__ __forceinline__ void tf32split(uint32_t raw, uint32_t& hi, uint32_t& lo) {
    float f = __uint_as_float(raw);
    uint32_t h = f2tf32(f);
    float r = f - __uint_as_float(h);   /* exact */
    hi = h;
    lo = f2tf32(r);
}

#define MMA_TF32(acc, a0, a1, a2, a3, b0, b1)                                  \
    asm volatile(                                                              \
        "mma.sync.aligned.m16n8k8.row.col.f32.tf32.tf32.f32 "                  \
        "{%0,%1,%2,%3}, {%4,%5,%6,%7}, {%8,%9}, {%0,%1,%2,%3};"                \
        : "+f"(acc[0]), "+f"(acc[1]), "+f"(acc[2]), "+f"(acc[3])               \
        : "r"(a0), "r"(a1), "r"(a2), "r"(a3), "r"(b0), "r"(b1))

/* ========= tf32 mma.sync NT GEMM: C[m,n] = sum_k A[m,k]B[n,k] ============= */
/* CTA 128x128, BK=32, 256 thr = 8 warps, warp tile 64x32 (m16n8k8 grid 4x4). */
/* PREC3=1: 3xTF32 split (fp32-accurate), passes interleaved so the 16       */
/* independent (mi,ni) MMAs sit between dependent accumulator updates.        */
/* PREC3=0: single-pass tf32 (used for the final LM head only).               */
/* mode 0: C = acc ; mode 1: C += acc ; mode 2: C = softplus(acc + bias[n])   */
#define BKP 36
#define TILE_U32 (128 * BKP)              /* 4608 u32 = 18432 B */

template <int PREC3>
__global__ void __launch_bounds__(256)
tmma_nt(const float* __restrict__ A, int lda,
        const float* __restrict__ B, int ldb,
        float* __restrict__ C, int ldc,
        int N, int K, int mode, const float* __restrict__ bias) {
    extern __shared__ uint32_t smem[];
    uint32_t* Abuf[2] = { smem,                smem + 2 * TILE_U32 };
    uint32_t* Bbuf[2] = { smem + TILE_U32,     smem + 3 * TILE_U32 };

    const int tid = threadIdx.x;
    const int wid = tid >> 5;
    const int lane = tid & 31;
    const int g = lane >> 2;               /* groupID 0..7 */
    const int t = lane & 3;                /* threadID_in_group */
    const int m0 = blockIdx.y * 128;
    const int n0 = blockIdx.x * 128;
    const int wm = (wid & 1) * 64;         /* warp M offset  */
    const int wn = (wid >> 1) * 32;        /* warp N offset  */

    /* loader mapping: row = tid/2, col base = (tid&1)*16 */
    const int lrow = tid >> 1;
    const int lcol = (tid & 1) * 16;
    const float* aptr = A + (size_t)(m0 + lrow) * lda + lcol;
    const int brow_g = n0 + lrow;
    const float* bptr = B + (size_t)brow_g * ldb + lcol;
    const bool bvalid = (brow_g < N);
    const uint32_t soff = (uint32_t)lrow * BKP + lcol;

    float acc[4][4][4];
#pragma unroll
    for (int mi = 0; mi < 4; mi++)
#pragma unroll
        for (int ni = 0; ni < 4; ni++)
#pragma unroll
            for (int q = 0; q < 4; q++) acc[mi][ni][q] = 0.f;

    const int nk = K >> 5;

    /* preload tile 0 (raw fp32 bits into SMEM) */
    float4 ar[4], br[4];
#pragma unroll
    for (int f = 0; f < 4; f++) {
        ar[f] = *(const float4*)(aptr + f * 4);
        br[f] = bvalid ? *(const float4*)(bptr + f * 4)
                       : make_float4(0.f, 0.f, 0.f, 0.f);
    }
    {
        float* As = (float*)Abuf[0];
        float* Bs = (float*)Bbuf[0];
#pragma unroll
        for (int f = 0; f < 4; f++) {
            As[soff + f * 4 + 0] = ar[f].x; As[soff + f * 4 + 1] = ar[f].y;
            As[soff + f * 4 + 2] = ar[f].z; As[soff + f * 4 + 3] = ar[f].w;
            Bs[soff + f * 4 + 0] = br[f].x; Bs[soff + f * 4 + 1] = br[f].y;
            Bs[soff + f * 4 + 2] = br[f].z; Bs[soff + f * 4 + 3] = br[f].w;
        }
    }
    __syncthreads();

    for (int kt = 0; kt < nk; kt++) {
        const int cur = kt & 1;
        /* prefetch next k-tile into registers (overlaps with MMA below) */
        if (kt + 1 < nk) {
            const float* ap = aptr + (kt + 1) * 32;
            const float* bp = bptr + (kt + 1) * 32;
#pragma unroll
            for (int f = 0; f < 4; f++) {
                ar[f] = *(const float4*)(ap + f * 4);
                br[f] = bvalid ? *(const float4*)(bp + f * 4)
                               : make_float4(0.f, 0.f, 0.f, 0.f);
            }
        }

        const uint32_t* As = Abuf[cur];
        const uint32_t* Bs = Bbuf[cur];
#pragma unroll
        for (int ks = 0; ks < 4; ks++) {
            const int k8 = ks * 8;
            if (PREC3) {
                uint32_t ah[4][4], al[4][4], bh[4][2], bl[4][2];
#pragma unroll
                for (int mi = 0; mi < 4; mi++) {
                    const int r = wm + mi * 16 + g;
                    tf32split(As[r * BKP + k8 + t],           ah[mi][0], al[mi][0]);
                    tf32split(As[(r + 8) * BKP + k8 + t],     ah[mi][1], al[mi][1]);
                    tf32split(As[r * BKP + k8 + t + 4],       ah[mi][2], al[mi][2]);
                    tf32split(As[(r + 8) * BKP + k8 + t + 4], ah[mi][3], al[mi][3]);
                }
#pragma unroll
                for (int ni = 0; ni < 4; ni++) {
                    const int n = wn + ni * 8 + g;
                    tf32split(Bs[n * BKP + k8 + t],     bh[ni][0], bl[ni][0]);
                    tf32split(Bs[n * BKP + k8 + t + 4], bh[ni][1], bl[ni][1]);
                }
                /* pass 1: ah x bl -- 16 independent MMAs */
#pragma unroll
                for (int mi = 0; mi < 4; mi++)
#pragma unroll
                    for (int ni = 0; ni < 4; ni++)
                        MMA_TF32(acc[mi][ni], ah[mi][0], ah[mi][1], ah[mi][2],
                                 ah[mi][3], bl[ni][0], bl[ni][1]);
                /* pass 2: al x bh */
#pragma unroll
                for (int mi = 0; mi < 4; mi++)
#pragma unroll
                    for (int ni = 0; ni < 4; ni++)
                        MMA_TF32(acc[mi][ni], al[mi][0], al[mi][1], al[mi][2],
                                 al[mi][3], bh[ni][0], bh[ni][1]);
                /* pass 3: ah x bh */
#pragma unroll
                for (int mi = 0; mi < 4; mi++)
#pragma unroll
                    for (int ni = 0; ni < 4; ni++)
                        MMA_TF32(acc[mi][ni], ah[mi][0], ah[mi][1], ah[mi][2],
                                 ah[mi][3], bh[ni][0], bh[ni][1]);
            } else {
                uint32_t af[4][4], bf[4][2];
#pragma unroll
                for (int mi = 0; mi < 4; mi++) {
                    const int r = wm + mi * 16 + g;
                    af[mi][0] = f2tf32(__uint_as_float(As[r * BKP + k8 + t]));
                    af[mi][1] = f2tf32(__uint_as_float(As[(r + 8) * BKP + k8 + t]));
                    af[mi][2] = f2tf32(__uint_as_float(As[r * BKP + k8 + t + 4]));
                    af[mi][3] = f2tf32(__uint_as_float(As[(r + 8) * BKP + k8 + t + 4]));
                }
#pragma unroll
                for (int ni = 0; ni < 4; ni++) {
                    const int n = wn + ni * 8 + g;
                    bf[ni][0] = f2tf32(__uint_as_float(Bs[n * BKP + k8 + t]));
                    bf[ni][1] = f2tf32(__uint_as_float(Bs[n * BKP + k8 + t + 4]));
                }
#pragma unroll
                for (int mi = 0; mi < 4; mi++)
#pragma unroll
                    for (int ni = 0; ni < 4; ni++)
                        MMA_TF32(acc[mi][ni], af[mi][0], af[mi][1], af[mi][2],
                                 af[mi][3], bf[ni][0], bf[ni][1]);
            }
        }

        /* stage next tile into the other buffer */
        if (kt + 1 < nk) {
            float* An = (float*)Abuf[cur ^ 1];
            float* Bn = (float*)Bbuf[cur ^ 1];
#pragma unroll
            for (int f = 0; f < 4; f++) {
                An[soff + f * 4 + 0] = ar[f].x; An[soff + f * 4 + 1] = ar[f].y;
                An[soff + f * 4 + 2] = ar[f].z; An[soff + f * 4 + 3] = ar[f].w;
                Bn[soff + f * 4 + 0] = br[f].x; Bn[soff + f * 4 + 1] = br[f].y;
                Bn[soff + f * 4 + 2] = br[f].z; Bn[soff + f * 4 + 3] = br[f].w;
            }
            __syncthreads();
        }
    }

    /* ---- epilogue: c0,c1 at (row g, cols 2t,2t+1); c2,c3 at row g+8 ------ */
    /* float2 only when (m*ldc + n) is even: ldc may be ODD (VOCAB=50257).    */
#pragma unroll
    for (int mi = 0; mi < 4; mi++) {
#pragma unroll
        for (int ni = 0; ni < 4; ni++) {
            const int m = m0 + wm + mi * 16 + g;
            const int n = n0 + wn + ni * 8 + t * 2;
            if (n < N) {
                float v0x = acc[mi][ni][0], v0y = acc[mi][ni][1];
                float v1x = acc[mi][ni][2], v1y = acc[mi][ni][3];
                float* p0 = C + (size_t)m * ldc + n;
                float* p1 = C + (size_t)(m + 8) * ldc + n;
                const bool al2 = ((((size_t)m * (size_t)ldc + (size_t)n) & 1) == 0);
                if (n + 1 < N) {
                    if (al2) {
                        float2 v0 = make_float2(v0x, v0y);
                        float2 v1 = make_float2(v1x, v1y);
                        if (mode == 1) {
                            float2 o0 = *(float2*)p0, o1 = *(float2*)p1;
                            v0.x += o0.x; v0.y += o0.y; v1.x += o1.x; v1.y += o1.y;
                        } else if (mode == 2) {
                            float b0 = bias[n], b1 = bias[n + 1];
                            v0.x = softplus_f(v0.x + b0); v0.y = softplus_f(v0.y + b1);
                            v1.x = softplus_f(v1.x + b0); v1.y = softplus_f(v1.y + b1);
                        }
                        *(float2*)p0 = v0;
                        *(float2*)p1 = v1;
                    } else {
                        if (mode == 1) {
                            v0x += p0[0]; v0y += p0[1];
                            v1x += p1[0]; v1y += p1[1];
                        } else if (mode == 2) {
                            float b0 = bias[n], b1 = bias[n + 1];
                            v0x = softplus_f(v0x + b0); v0y = softplus_f(v0y + b1);
                            v1x = softplus_f(v1x + b0); v1y = softplus_f(v1y + b1);
                        }
                        p0[0] = v0x; p0[1] = v0y;
                        p1[0] = v1x; p1[1] = v1y;
                    }
                } else {
                    if (mode == 1) { v0x += *p0; v1x += *p1; }
                    else if (mode == 2) {
                        float b0 = bias[n];
                        v0x = softplus_f(v0x + b0); v1x = softplus_f(v1x + b0);
                    }
                    *p0 = v0x;
                    *p1 = v1x;
                }
            }
        }
    }
}

/* ---------------- embedding gather --------------------------------------- */
__global__ void embed_kernel(const int* __restrict__ tok,
                             const float* __restrict__ W,
                             float* __restrict__ x) {
    int row = blockIdx.x;
    int t = tok[row];
    const float4* src = (const float4*)(W + (size_t)t * N_EMBD);
    float4* dst = (float4*)(x + (size_t)row * N_EMBD);
    dst[threadIdx.x] = src[threadIdx.x];
}

/* ---------------- rmsnorm: one block per row ------------------------------ */
__global__ void rmsnorm_kernel(const float* __restrict__ x,
                               const float* __restrict__ w,
                               const float* __restrict__ b,
                               float* __restrict__ out) {
    int row = blockIdx.x;
    const float4* xv = (const float4*)(x + (size_t)row * N_EMBD);
    float4 v = xv[threadIdx.x];
    float ss = v.x * v.x + v.y * v.y + v.z * v.z + v.w * v.w;
#pragma unroll
    for (int o = 16; o; o >>= 1) ss += __shfl_xor_sync(0xffffffffu, ss, o);
    __shared__ float red[8];
    if ((threadIdx.x & 31) == 0) red[threadIdx.x >> 5] = ss;
    __syncthreads();
    float tot = 0.f;
#pragma unroll
    for (int i = 0; i < 8; i++) tot += red[i];
    float inv = rsqrtf(tot * (1.f / N_EMBD) + 1e-6f);
    const float4* wv = (const float4*)w;
    const float4* bv = (const float4*)b;
    float4 ww = wv[threadIdx.x], bb = bv[threadIdx.x];
    float4 o4;
    o4.x = v.x * inv * ww.x + bb.x;
    o4.y = v.y * inv * ww.y + bb.y;
    o4.z = v.z * inv * ww.z + bb.z;
    o4.w = v.w * inv * ww.w + bb.w;
    ((float4*)(out + (size_t)row * N_EMBD))[threadIdx.x] = o4;
}

/* ---------------- depthwise causal conv (width 4) + silu ----------------- */
__global__ void conv_silu_kernel(const float* __restrict__ xr,
                                 const float* __restrict__ cw,
                                 const float* __restrict__ cb,
                                 float* __restrict__ xc) {
    int idx = blockIdx.x * blockDim.x + threadIdx.x;
    int t = idx >> 11;
    int d = idx & (D_INNER - 1);
    const float* w = cw + d * 4;
    float acc = cb[d];
#pragma unroll
    for (int j = 0; j < 4; j++) {
        int ti = t - 3 + j;
        float xv = (ti >= 0) ? xr[(size_t)ti * (2 * D_INNER) + d] : 0.f;
        acc += xv * w[j];
    }
    xc[idx] = silu_f(acc);
}

/* ---------------- selective scan: 16 lanes per channel -------------------- */
__global__ void scan_kernel(const float* __restrict__ xdbl,
                            const float* __restrict__ delta,
                            const float* __restrict__ xc,
                            const float* __restrict__ xr,
                            const float* __restrict__ A_log,
                            const float* __restrict__ Dp,
                            float* __restrict__ y) {
    int lane = threadIdx.x & 15;
    int ch = blockIdx.x * (blockDim.x >> 4) + (threadIdx.x >> 4);
    float Aval = -__expf(A_log[ch * D_STATE + lane]);
    float Dv = Dp[ch];
    float s = 0.f;
    for (int t = 0; t < L_SEQ; t++) {
        float dt = delta[(size_t)t * D_INNER + ch];
        float ut = xc[(size_t)t * D_INNER + ch];
        float Bt = xdbl[(size_t)t * XDBL + DT_RANK + lane];
        float Ct = xdbl[(size_t)t * XDBL + DT_RANK + D_STATE + lane];
        s = __expf(dt * Aval) * s + (dt * Bt) * ut;
        float v = s * Ct;
        v += __shfl_xor_sync(0xffffffffu, v, 8);
        v += __shfl_xor_sync(0xffffffffu, v, 4);
        v += __shfl_xor_sync(0xffffffffu, v, 2);
        v += __shfl_xor_sync(0xffffffffu, v, 1);
        if (lane == 0) {
            float r = xr[(size_t)t * (2 * D_INNER) + D_INNER + ch];
            y[(size_t)t * D_INNER + ch] = (v + ut * Dv) * silu_f(r);
        }
    }
}

/* ---------------- launcher ------------------------------------------------ */
#define TMMA_SMEM (4 * TILE_U32 * 4)   /* 73728 bytes */

static void launch_tmma(const float* A, int lda, const float* B, int ldb,
                        float* C, int ldc, int N, int K, int mode,
                        const float* bias) {
    dim3 grid((N + 127) / 128, L_SEQ / 128);
    tmma_nt<1><<<grid, 256, TMMA_SMEM>>>(A, lda, B, ldb, C, ldc, N, K, mode, bias);
}
static void launch_tmma_fast(const float* A, int lda, const float* B, int ldb,
                             float* C, int ldc, int N, int K, int mode,
                             const float* bias) {
    dim3 grid((N + 127) / 128, L_SEQ / 128);
    tmma_nt<0><<<grid, 256, TMMA_SMEM>>>(A, lda, B, ldb, C, ldc, N, K, mode, bias);
}

extern "C" void kernel_launch(void* const* d_in, const int* in_sizes, int n_in,
                              void* d_out, int out_size) {
    const int*   tokens   = (const int*)  d_in[0];
    const float* emb_W    = (const float*)d_in[1];
    const float* in_projW = (const float*)d_in[2];
    const float* conv_W   = (const float*)d_in[3];
    const float* conv_b   = (const float*)d_in[4];
    const float* xproj_W  = (const float*)d_in[5];
    const float* dt_W     = (const float*)d_in[6];
    const float* dt_b     = (const float*)d_in[7];
    const float* A_log    = (const float*)d_in[8];
    const float* Dp       = (const float*)d_in[9];
    const float* out_W    = (const float*)d_in[10];
    const float* rms_w    = (const float*)d_in[11];
    const float* rms_b    = (const float*)d_in[12];
    const float* normf_w  = (const float*)d_in[13];
    const float* normf_b  = (const float*)d_in[14];
    float* out = (float*)d_out;

    cudaFuncSetAttribute(tmma_nt<1>, cudaFuncAttributeMaxDynamicSharedMemorySize,
                         TMMA_SMEM);
    cudaFuncSetAttribute(tmma_nt<0>, cudaFuncAttributeMaxDynamicSharedMemorySize,
                         TMMA_SMEM);

    float *x, *h, *xr, *xc, *xdbl, *delta, *y;
    cudaGetSymbolAddress((void**)&x,     g_x);
    cudaGetSymbolAddress((void**)&h,     g_h);
    cudaGetSymbolAddress((void**)&xr,    g_xr);
    cudaGetSymbolAddress((void**)&xc,    g_xc);
    cudaGetSymbolAddress((void**)&xdbl,  g_xdbl);
    cudaGetSymbolAddress((void**)&delta, g_delta);
    cudaGetSymbolAddress((void**)&y,     g_y);

    embed_kernel<<<L_SEQ, 256>>>(tokens, emb_W, x);

    for (int i = 0; i < N_LAYERS; i++) {
        rmsnorm_kernel<<<L_SEQ, 256>>>(x, rms_w + i * N_EMBD, rms_b + i * N_EMBD, h);
        /* xr = h @ in_proj_W^T   [2048 x 4096 x 1024] */
        launch_tmma(h, N_EMBD, in_projW + (size_t)i * 2 * D_INNER * N_EMBD, N_EMBD,
                    xr, 2 * D_INNER, 2 * D_INNER, N_EMBD, 0, nullptr);
        conv_silu_kernel<<<L_SEQ * D_INNER / 256, 256>>>(
            xr, conv_W + (size_t)i * D_INNER * D_CONV, conv_b + i * D_INNER, xc);
        /* x_dbl = xc @ xproj_W^T   [2048 x 96 x 2048] */
        launch_tmma(xc, D_INNER, xproj_W + (size_t)i * XDBL * D_INNER, D_INNER,
                    xdbl, XDBL, XDBL, D_INNER, 0, nullptr);
        /* delta = softplus(x_dbl[:, :64] @ dt_W^T + dt_b)   [2048 x 2048 x 64] */
        launch_tmma(xdbl, XDBL, dt_W + (size_t)i * D_INNER * DT_RANK, DT_RANK,
                    delta, D_INNER, D_INNER, DT_RANK, 2, dt_b + i * D_INNER);
        scan_kernel<<<D_INNER / 8, 128>>>(
            xdbl, delta, xc, xr,
            A_log + (size_t)i * D_INNER * D_STATE, Dp + i * D_INNER, y);
        /* x += y @ out_W^T   [2048 x 1024 x 2048] */
        launch_tmma(y, D_INNER, out_W + (size_t)i * N_EMBD * D_INNER, D_INNER,
                    x, N_EMBD, N_EMBD, D_INNER, 1, nullptr);
    }

    rmsnorm_kernel<<<L_SEQ, 256>>>(x, normf_w, normf_b, h);
    /* tied LM head (single-pass tf32 -- error does not compound further):
       out = h @ emb_W^T   [2048 x 50257 x 1024] */
    launch_tmma_fast(h, N_EMBD, emb_W, N_EMBD, out, VOCAB, VOCAB, N_EMBD, 0, nullptr);
}

// round 12
// speedup vs baseline: 1.4706x; 1.2241x over previous
#include <cuda_runtime.h>
#include <cuda_fp16.h>
#include <math.h>
#include <stdint.h>

#define L_SEQ   2048
#define N_EMBD  1024
#define D_INNER 2048
#define D_STATE 16
#define DT_RANK 64
#define D_CONV  4
#define XDBL    (DT_RANK + 2 * D_STATE)   /* 96 */
#define VOCAB   50257
#define N_LAYERS 4

/* ---------------- scratch (static device allocations, allowed) ------------ */
__device__ float g_x[L_SEQ * N_EMBD];
__device__ float g_h[L_SEQ * N_EMBD];
__device__ float g_xr[L_SEQ * 2 * D_INNER];
__device__ float g_xc[L_SEQ * D_INNER];
__device__ float g_xdbl[L_SEQ * XDBL];
__device__ float g_delta[L_SEQ * D_INNER];
__device__ float g_y[L_SEQ * D_INNER];

__device__ __forceinline__ float silu_f(float v) { return v / (1.f + __expf(-v)); }
__device__ __forceinline__ float softplus_f(float v) {
    if (v > 20.f) return v;
    return log1pf(__expf(v));
}
__device__ __forceinline__ uint32_t h2_u32(half2 h) {
    uint32_t u;
    asm("mov.b32 %0, %1;" : "=r"(u) : "r"(*(uint32_t*)&h));
    return u;
}

/* NOT volatile: pure dataflow through "+f" lets ptxas schedule HMMAs */
#define MMA_F16(acc, a0, a1, a2, a3, b0, b1)                                   \
    asm("mma.sync.aligned.m16n8k16.row.col.f32.f16.f16.f32 "                   \
        "{%0,%1,%2,%3}, {%4,%5,%6,%7}, {%8,%9}, {%0,%1,%2,%3};"                \
        : "+f"(acc[0]), "+f"(acc[1]), "+f"(acc[2]), "+f"(acc[3])               \
        : "r"(a0), "r"(a1), "r"(a2), "r"(a3), "r"(b0), "r"(b1))

/* ===== fp16 m16n8k16 NT GEMM: C[m,n] = sum_k A[m,k]B[n,k], f32 accum ====== */
/* CTA 128x128, BK=32, 256 thr = 8 warps, warp tile 64x32.                    */
/* PREC3=1: 2-term fp16 split (hi+lo), 3 passes -> ~fp32 accuracy.            */
/* PREC3=0: single-pass fp16 (same 10-bit mantissa class as tf32) - LM head.  */
/* SMEM tiles hold half2 words, row stride 20 words (fragment LDS conflict-   */
/* free: (20g+t) mod 32 distinct). hi/lo split done ONCE at staging.          */
/* mode 0: C = acc ; mode 1: C += acc ; mode 2: C = softplus(acc + bias[n])   */
#define SW      20                        /* words per row (16 data + 4 pad)  */
#define TILE_W  (128 * SW)                /* 2560 u32 per tile                */

template <int PREC3>
__global__ void __launch_bounds__(256)
hmma_nt(const float* __restrict__ A, int lda,
        const float* __restrict__ B, int ldb,
        float* __restrict__ C, int ldc,
        int N, int K, int mode, const float* __restrict__ bias) {
    extern __shared__ uint32_t smem[];
    constexpr int NT   = PREC3 ? 4 : 2;   /* tiles per buffer */
    constexpr int BUFW = NT * TILE_W;

    const int tid = threadIdx.x;
    const int wid = tid >> 5;
    const int lane = tid & 31;
    const int g = lane >> 2;               /* groupID 0..7 */
    const int t = lane & 3;                /* threadID_in_group */
    const int m0 = blockIdx.y * 128;
    const int n0 = blockIdx.x * 128;
    const int wm = (wid & 1) * 64;         /* warp M offset  */
    const int wn = (wid >> 1) * 32;        /* warp N offset  */

    /* loader mapping: row = tid&127, half = tid>>7 (16 floats each) */
    const int lrow = tid & 127;
    const int lhalf = tid >> 7;
    const float* aptr = A + (size_t)(m0 + lrow) * lda + lhalf * 16;
    const int brow_g = n0 + lrow;
    const float* bptr = B + (size_t)brow_g * ldb + lhalf * 16;
    const bool bvalid = (brow_g < N);
    const uint32_t soff = (uint32_t)lrow * SW + lhalf * 8;

    float acc[4][4][4];
#pragma unroll
    for (int mi = 0; mi < 4; mi++)
#pragma unroll
        for (int ni = 0; ni < 4; ni++)
#pragma unroll
            for (int q = 0; q < 4; q++) acc[mi][ni][q] = 0.f;

    const int nk = K >> 5;

    float4 ar[4], br[4];
#pragma unroll
    for (int f = 0; f < 4; f++) {
        ar[f] = *(const float4*)(aptr + f * 4);
        br[f] = bvalid ? *(const float4*)(bptr + f * 4)
                       : make_float4(0.f, 0.f, 0.f, 0.f);
    }

    /* stage tile 0 */
    {
        uint32_t* Ah = smem;
        uint32_t* Bh = smem + (PREC3 ? 2 : 1) * TILE_W;
#pragma unroll
        for (int f = 0; f < 4; f++) {
            half2 ha = __floats2half2_rn(ar[f].x, ar[f].y);
            half2 hb = __floats2half2_rn(ar[f].z, ar[f].w);
            Ah[soff + f * 2 + 0] = h2_u32(ha);
            Ah[soff + f * 2 + 1] = h2_u32(hb);
            half2 hc = __floats2half2_rn(br[f].x, br[f].y);
            half2 hd = __floats2half2_rn(br[f].z, br[f].w);
            Bh[soff + f * 2 + 0] = h2_u32(hc);
            Bh[soff + f * 2 + 1] = h2_u32(hd);
            if (PREC3) {
                uint32_t* Al = smem + TILE_W;
                uint32_t* Bl = smem + 3 * TILE_W;
                half2 la = __floats2half2_rn(ar[f].x - __low2float(ha),
                                             ar[f].y - __high2float(ha));
                half2 lb = __floats2half2_rn(ar[f].z - __low2float(hb),
                                             ar[f].w - __high2float(hb));
                Al[soff + f * 2 + 0] = h2_u32(la);
                Al[soff + f * 2 + 1] = h2_u32(lb);
                half2 lc = __floats2half2_rn(br[f].x - __low2float(hc),
                                             br[f].y - __high2float(hc));
                half2 ld = __floats2half2_rn(br[f].z - __low2float(hd),
                                             br[f].w - __high2float(hd));
                Bl[soff + f * 2 + 0] = h2_u32(lc);
                Bl[soff + f * 2 + 1] = h2_u32(ld);
            }
        }
    }
    __syncthreads();

    for (int kt = 0; kt < nk; kt++) {
        const int cur = kt & 1;
        /* prefetch next k-tile into registers (overlaps MMA below) */
        if (kt + 1 < nk) {
            const float* ap = aptr + (kt + 1) * 32;
            const float* bp = bptr + (kt + 1) * 32;
#pragma unroll
            for (int f = 0; f < 4; f++) {
                ar[f] = *(const float4*)(ap + f * 4);
                br[f] = bvalid ? *(const float4*)(bp + f * 4)
                               : make_float4(0.f, 0.f, 0.f, 0.f);
            }
        }

        const uint32_t* Ah = smem + cur * BUFW;
        const uint32_t* Al = Ah + TILE_W;                  /* PREC3 only */
        const uint32_t* Bh = Ah + (PREC3 ? 2 : 1) * TILE_W;
        const uint32_t* Bl = Bh + TILE_W;                  /* PREC3 only */

#pragma unroll
        for (int ks = 0; ks < 2; ks++) {                   /* K=16 each */
            const int kb = ks * 8;
            uint32_t ah[4][4], bh[4][2];
#pragma unroll
            for (int mi = 0; mi < 4; mi++) {
                const int w0 = (wm + mi * 16 + g) * SW + kb + t;
                ah[mi][0] = Ah[w0];       ah[mi][1] = Ah[w0 + 8 * SW];
                ah[mi][2] = Ah[w0 + 4];   ah[mi][3] = Ah[w0 + 8 * SW + 4];
            }
#pragma unroll
            for (int ni = 0; ni < 4; ni++) {
                const int w0 = (wn + ni * 8 + g) * SW + kb + t;
                bh[ni][0] = Bh[w0];       bh[ni][1] = Bh[w0 + 4];
            }
            if (PREC3) {
                uint32_t al[4][4], bl[4][2];
#pragma unroll
                for (int mi = 0; mi < 4; mi++) {
                    const int w0 = (wm + mi * 16 + g) * SW + kb + t;
                    al[mi][0] = Al[w0];     al[mi][1] = Al[w0 + 8 * SW];
                    al[mi][2] = Al[w0 + 4]; al[mi][3] = Al[w0 + 8 * SW + 4];
                }
#pragma unroll
                for (int ni = 0; ni < 4; ni++) {
                    const int w0 = (wn + ni * 8 + g) * SW + kb + t;
                    bl[ni][0] = Bl[w0];     bl[ni][1] = Bl[w0 + 4];
                }
                /* hi x lo */
#pragma unroll
                for (int mi = 0; mi < 4; mi++)
#pragma unroll
                    for (int ni = 0; ni < 4; ni++)
                        MMA_F16(acc[mi][ni], ah[mi][0], ah[mi][1], ah[mi][2],
                                ah[mi][3], bl[ni][0], bl[ni][1]);
                /* lo x hi */
#pragma unroll
                for (int mi = 0; mi < 4; mi++)
#pragma unroll
                    for (int ni = 0; ni < 4; ni++)
                        MMA_F16(acc[mi][ni], al[mi][0], al[mi][1], al[mi][2],
                                al[mi][3], bh[ni][0], bh[ni][1]);
            }
            /* hi x hi */
#pragma unroll
            for (int mi = 0; mi < 4; mi++)
#pragma unroll
                for (int ni = 0; ni < 4; ni++)
                    MMA_F16(acc[mi][ni], ah[mi][0], ah[mi][1], ah[mi][2],
                            ah[mi][3], bh[ni][0], bh[ni][1]);
        }

        /* stage next tile into the other buffer */
        if (kt + 1 < nk) {
            uint32_t* An = smem + (cur ^ 1) * BUFW;
            uint32_t* Bn = An + (PREC3 ? 2 : 1) * TILE_W;
            __syncthreads();   /* tile consumed before overwrite */
#pragma unroll
            for (int f = 0; f < 4; f++) {
                half2 ha = __floats2half2_rn(ar[f].x, ar[f].y);
                half2 hb = __floats2half2_rn(ar[f].z, ar[f].w);
                An[soff + f * 2 + 0] = h2_u32(ha);
                An[soff + f * 2 + 1] = h2_u32(hb);
                half2 hc = __floats2half2_rn(br[f].x, br[f].y);
                half2 hd = __floats2half2_rn(br[f].z, br[f].w);
                Bn[soff + f * 2 + 0] = h2_u32(hc);
                Bn[soff + f * 2 + 1] = h2_u32(hd);
                if (PREC3) {
                    uint32_t* Aln = An + TILE_W;
                    uint32_t* Bln = Bn + TILE_W;
                    half2 la = __floats2half2_rn(ar[f].x - __low2float(ha),
                                                 ar[f].y - __high2float(ha));
                    half2 lb = __floats2half2_rn(ar[f].z - __low2float(hb),
                                                 ar[f].w - __high2float(hb));
                    Aln[soff + f * 2 + 0] = h2_u32(la);
                    Aln[soff + f * 2 + 1] = h2_u32(lb);
                    half2 lc = __floats2half2_rn(br[f].x - __low2float(hc),
                                                 br[f].y - __high2float(hc));
                    half2 ld = __floats2half2_rn(br[f].z - __low2float(hd),
                                                 br[f].w - __high2float(hd));
                    Bln[soff + f * 2 + 0] = h2_u32(lc);
                    Bln[soff + f * 2 + 1] = h2_u32(ld);
                }
            }
            __syncthreads();
        }
    }

    /* ---- epilogue: c0,c1 at (row g, cols 2t,2t+1); c2,c3 at row g+8 ------ */
    /* float2 only when (m*ldc + n) even: ldc may be ODD (VOCAB=50257).       */
#pragma unroll
    for (int mi = 0; mi < 4; mi++) {
#pragma unroll
        for (int ni = 0; ni < 4; ni++) {
            const int m = m0 + wm + mi * 16 + g;
            const int n = n0 + wn + ni * 8 + t * 2;
            if (n < N) {
                float v0x = acc[mi][ni][0], v0y = acc[mi][ni][1];
                float v1x = acc[mi][ni][2], v1y = acc[mi][ni][3];
                float* p0 = C + (size_t)m * ldc + n;
                float* p1 = C + (size_t)(m + 8) * ldc + n;
                const bool al2 = ((((size_t)m * (size_t)ldc + (size_t)n) & 1) == 0);
                if (n + 1 < N) {
                    if (al2) {
                        float2 v0 = make_float2(v0x, v0y);
                        float2 v1 = make_float2(v1x, v1y);
                        if (mode == 1) {
                            float2 o0 = *(float2*)p0, o1 = *(float2*)p1;
                            v0.x += o0.x; v0.y += o0.y; v1.x += o1.x; v1.y += o1.y;
                        } else if (mode == 2) {
                            float b0 = bias[n], b1 = bias[n + 1];
                            v0.x = softplus_f(v0.x + b0); v0.y = softplus_f(v0.y + b1);
                            v1.x = softplus_f(v1.x + b0); v1.y = softplus_f(v1.y + b1);
                        }
                        *(float2*)p0 = v0;
                        *(float2*)p1 = v1;
                    } else {
                        if (mode == 1) {
                            v0x += p0[0]; v0y += p0[1];
                            v1x += p1[0]; v1y += p1[1];
                        } else if (mode == 2) {
                            float b0 = bias[n], b1 = bias[n + 1];
                            v0x = softplus_f(v0x + b0); v0y = softplus_f(v0y + b1);
                            v1x = softplus_f(v1x + b0); v1y = softplus_f(v1y + b1);
                        }
                        p0[0] = v0x; p0[1] = v0y;
                        p1[0] = v1x; p1[1] = v1y;
                    }
                } else {
                    if (mode == 1) { v0x += *p0; v1x += *p1; }
                    else if (mode == 2) {
                        float b0 = bias[n];
                        v0x = softplus_f(v0x + b0); v1x = softplus_f(v1x + b0);
                    }
                    *p0 = v0x;
                    *p1 = v1x;
                }
            }
        }
    }
}

/* ---------------- embedding gather --------------------------------------- */
__global__ void embed_kernel(const int* __restrict__ tok,
                             const float* __restrict__ W,
                             float* __restrict__ x) {
    int row = blockIdx.x;
    int t = tok[row];
    const float4* src = (const float4*)(W + (size_t)t * N_EMBD);
    float4* dst = (float4*)(x + (size_t)row * N_EMBD);
    dst[threadIdx.x] = src[threadIdx.x];
}

/* ---------------- rmsnorm: one block per row ------------------------------ */
__global__ void rmsnorm_kernel(const float* __restrict__ x,
                               const float* __restrict__ w,
                               const float* __restrict__ b,
                               float* __restrict__ out) {
    int row = blockIdx.x;
    const float4* xv = (const float4*)(x + (size_t)row * N_EMBD);
    float4 v = xv[threadIdx.x];
    float ss = v.x * v.x + v.y * v.y + v.z * v.z + v.w * v.w;
#pragma unroll
    for (int o = 16; o; o >>= 1) ss += __shfl_xor_sync(0xffffffffu, ss, o);
    __shared__ float red[8];
    if ((threadIdx.x & 31) == 0) red[threadIdx.x >> 5] = ss;
    __syncthreads();
    float tot = 0.f;
#pragma unroll
    for (int i = 0; i < 8; i++) tot += red[i];
    float inv = rsqrtf(tot * (1.f / N_EMBD) + 1e-6f);
    const float4* wv = (const float4*)w;
    const float4* bv = (const float4*)b;
    float4 ww = wv[threadIdx.x], bb = bv[threadIdx.x];
    float4 o4;
    o4.x = v.x * inv * ww.x + bb.x;
    o4.y = v.y * inv * ww.y + bb.y;
    o4.z = v.z * inv * ww.z + bb.z;
    o4.w = v.w * inv * ww.w + bb.w;
    ((float4*)(out + (size_t)row * N_EMBD))[threadIdx.x] = o4;
}

/* ---------------- depthwise causal conv (width 4) + silu ----------------- */
__global__ void conv_silu_kernel(const float* __restrict__ xr,
                                 const float* __restrict__ cw,
                                 const float* __restrict__ cb,
                                 float* __restrict__ xc) {
    int idx = blockIdx.x * blockDim.x + threadIdx.x;
    int t = idx >> 11;
    int d = idx & (D_INNER - 1);
    const float* w = cw + d * 4;
    float acc = cb[d];
#pragma unroll
    for (int j = 0; j < 4; j++) {
        int ti = t - 3 + j;
        float xv = (ti >= 0) ? xr[(size_t)ti * (2 * D_INNER) + d] : 0.f;
        acc += xv * w[j];
    }
    xc[idx] = silu_f(acc);
}

/* ---------------- selective scan: 16 lanes per channel -------------------- */
__global__ void scan_kernel(const float* __restrict__ xdbl,
                            const float* __restrict__ delta,
                            const float* __restrict__ xc,
                            const float* __restrict__ xr,
                            const float* __restrict__ A_log,
                            const float* __restrict__ Dp,
                            float* __restrict__ y) {
    int lane = threadIdx.x & 15;
    int ch = blockIdx.x * (blockDim.x >> 4) + (threadIdx.x >> 4);
    float Aval = -__expf(A_log[ch * D_STATE + lane]);
    float Dv = Dp[ch];
    float s = 0.f;
    for (int t = 0; t < L_SEQ; t++) {
        float dt = delta[(size_t)t * D_INNER + ch];
        float ut = xc[(size_t)t * D_INNER + ch];
        float Bt = xdbl[(size_t)t * XDBL + DT_RANK + lane];
        float Ct = xdbl[(size_t)t * XDBL + DT_RANK + D_STATE + lane];
        s = __expf(dt * Aval) * s + (dt * Bt) * ut;
        float v = s * Ct;
        v += __shfl_xor_sync(0xffffffffu, v, 8);
        v += __shfl_xor_sync(0xffffffffu, v, 4);
        v += __shfl_xor_sync(0xffffffffu, v, 2);
        v += __shfl_xor_sync(0xffffffffu, v, 1);
        if (lane == 0) {
            float r = xr[(size_t)t * (2 * D_INNER) + D_INNER + ch];
            y[(size_t)t * D_INNER + ch] = (v + ut * Dv) * silu_f(r);
        }
    }
}

/* ---------------- launcher ------------------------------------------------ */
#define SMEM_P3 (2 * 4 * TILE_W * 4)   /* 81920 B */
#define SMEM_P1 (2 * 2 * TILE_W * 4)   /* 40960 B */

static void launch_hmma(const float* A, int lda, const float* B, int ldb,
                        float* C, int ldc, int N, int K, int mode,
                        const float* bias) {
    dim3 grid((N + 127) / 128, L_SEQ / 128);
    hmma_nt<1><<<grid, 256, SMEM_P3>>>(A, lda, B, ldb, C, ldc, N, K, mode, bias);
}
static void launch_hmma_fast(const float* A, int lda, const float* B, int ldb,
                             float* C, int ldc, int N, int K, int mode,
                             const float* bias) {
    dim3 grid((N + 127) / 128, L_SEQ / 128);
    hmma_nt<0><<<grid, 256, SMEM_P1>>>(A, lda, B, ldb, C, ldc, N, K, mode, bias);
}

extern "C" void kernel_launch(void* const* d_in, const int* in_sizes, int n_in,
                              void* d_out, int out_size) {
    const int*   tokens   = (const int*)  d_in[0];
    const float* emb_W    = (const float*)d_in[1];
    const float* in_projW = (const float*)d_in[2];
    const float* conv_W   = (const float*)d_in[3];
    const float* conv_b   = (const float*)d_in[4];
    const float* xproj_W  = (const float*)d_in[5];
    const float* dt_W     = (const float*)d_in[6];
    const float* dt_b     = (const float*)d_in[7];
    const float* A_log    = (const float*)d_in[8];
    const float* Dp       = (const float*)d_in[9];
    const float* out_W    = (const float*)d_in[10];
    const float* rms_w    = (const float*)d_in[11];
    const float* rms_b    = (const float*)d_in[12];
    const float* normf_w  = (const float*)d_in[13];
    const float* normf_b  = (const float*)d_in[14];
    float* out = (float*)d_out;

    cudaFuncSetAttribute(hmma_nt<1>, cudaFuncAttributeMaxDynamicSharedMemorySize,
                         SMEM_P3);
    cudaFuncSetAttribute(hmma_nt<0>, cudaFuncAttributeMaxDynamicSharedMemorySize,
                         SMEM_P1);

    float *x, *h, *xr, *xc, *xdbl, *delta, *y;
    cudaGetSymbolAddress((void**)&x,     g_x);
    cudaGetSymbolAddress((void**)&h,     g_h);
    cudaGetSymbolAddress((void**)&xr,    g_xr);
    cudaGetSymbolAddress((void**)&xc,    g_xc);
    cudaGetSymbolAddress((void**)&xdbl,  g_xdbl);
    cudaGetSymbolAddress((void**)&delta, g_delta);
    cudaGetSymbolAddress((void**)&y,     g_y);

    embed_kernel<<<L_SEQ, 256>>>(tokens, emb_W, x);

    for (int i = 0; i < N_LAYERS; i++) {
        rmsnorm_kernel<<<L_SEQ, 256>>>(x, rms_w + i * N_EMBD, rms_b + i * N_EMBD, h);
        /* xr = h @ in_proj_W^T   [2048 x 4096 x 1024] */
        launch_hmma(h, N_EMBD, in_projW + (size_t)i * 2 * D_INNER * N_EMBD, N_EMBD,
                    xr, 2 * D_INNER, 2 * D_INNER, N_EMBD, 0, nullptr);
        conv_silu_kernel<<<L_SEQ * D_INNER / 256, 256>>>(
            xr, conv_W + (size_t)i * D_INNER * D_CONV, conv_b + i * D_INNER, xc);
        /* x_dbl = xc @ xproj_W^T   [2048 x 96 x 2048] */
        launch_hmma(xc, D_INNER, xproj_W + (size_t)i * XDBL * D_INNER, D_INNER,
                    xdbl, XDBL, XDBL, D_INNER, 0, nullptr);
        /* delta = softplus(x_dbl[:, :64] @ dt_W^T + dt_b)   [2048 x 2048 x 64] */
        launch_hmma(xdbl, XDBL, dt_W + (size_t)i * D_INNER * DT_RANK, DT_RANK,
                    delta, D_INNER, D_INNER, DT_RANK, 2, dt_b + i * D_INNER);
        scan_kernel<<<D_INNER / 8, 128>>>(
            xdbl, delta, xc, xr,
            A_log + (size_t)i * D_INNER * D_STATE, Dp + i * D_INNER, y);
        /* x += y @ out_W^T   [2048 x 1024 x 2048] */
        launch_hmma(y, D_INNER, out_W + (size_t)i * N_EMBD * D_INNER, D_INNER,
                    x, N_EMBD, N_EMBD, D_INNER, 1, nullptr);
    }

    rmsnorm_kernel<<<L_SEQ, 256>>>(x, normf_w, normf_b, h);
    /* tied LM head (single-pass fp16, same mantissa class as tf32):
       out = h @ emb_W^T   [2048 x 50257 x 1024] */
    launch_hmma_fast(h, N_EMBD, emb_W, N_EMBD, out, VOCAB, VOCAB, N_EMBD, 0, nullptr);
}

// round 14
// speedup vs baseline: 1.9018x; 1.2932x over previous
#include <cuda_runtime.h>
#include <cuda_fp16.h>
#include <math.h>
#include <stdint.h>

#define L_SEQ   2048
#define N_EMBD  1024
#define D_INNER 2048
#define D_STATE 16
#define DT_RANK 64
#define D_CONV  4
#define XDBL    (DT_RANK + 2 * D_STATE)   /* 96 */
#define VOCAB   50257
#define N_LAYERS 4

/* ---------------- fp32 scratch ------------------------------------------- */
__device__ float g_x[L_SEQ * N_EMBD];
__device__ float g_h[L_SEQ * N_EMBD];
__device__ float g_xr[L_SEQ * 2 * D_INNER];
__device__ float g_xc[L_SEQ * D_INNER];
__device__ float g_xdbl[L_SEQ * XDBL];
__device__ float g_delta[L_SEQ * D_INNER];
__device__ float g_y[L_SEQ * D_INNER];

/* ---------------- fp16 hi/lo mirrors (split once per use) ----------------- */
__device__ __align__(128) half g_h_hi[L_SEQ * N_EMBD];
__device__ __align__(128) half g_h_lo[L_SEQ * N_EMBD];
__device__ __align__(128) half g_xc_hi[L_SEQ * D_INNER];
__device__ __align__(128) half g_xc_lo[L_SEQ * D_INNER];
__device__ __align__(128) half g_xdbl_hi[L_SEQ * XDBL];
__device__ __align__(128) half g_xdbl_lo[L_SEQ * XDBL];
__device__ __align__(128) half g_y_hi[L_SEQ * D_INNER];
__device__ __align__(128) half g_y_lo[L_SEQ * D_INNER];
__device__ __align__(128) half g_win_hi[N_LAYERS * 2 * D_INNER * N_EMBD];
__device__ __align__(128) half g_win_lo[N_LAYERS * 2 * D_INNER * N_EMBD];
__device__ __align__(128) half g_wxp_hi[N_LAYERS * XDBL * D_INNER];
__device__ __align__(128) half g_wxp_lo[N_LAYERS * XDBL * D_INNER];
__device__ __align__(128) half g_wdt_hi[N_LAYERS * D_INNER * DT_RANK];
__device__ __align__(128) half g_wdt_lo[N_LAYERS * D_INNER * DT_RANK];
__device__ __align__(128) half g_wout_hi[N_LAYERS * N_EMBD * D_INNER];
__device__ __align__(128) half g_wout_lo[N_LAYERS * N_EMBD * D_INNER];
__device__ __align__(128) half g_emb_hi[(size_t)VOCAB * N_EMBD];

__device__ __forceinline__ float silu_f(float v) { return v / (1.f + __expf(-v)); }
__device__ __forceinline__ float softplus_f(float v) {
    if (v > 20.f) return v;
    return log1pf(__expf(v));
}
__device__ __forceinline__ uint32_t smem_u32(const void* p) {
    uint32_t a;
    asm("{ .reg .u64 t; cvta.to.shared.u64 t, %1; cvt.u32.u64 %0, t; }"
        : "=r"(a) : "l"(p));
    return a;
}
__device__ __forceinline__ void cp16(uint32_t dst, const void* src) {
    asm volatile("cp.async.cg.shared.global [%0], [%1], 16;"
                 :: "r"(dst), "l"(src));
}

#define MMA_F16(acc, a0, a1, a2, a3, b0, b1)                                   \
    asm("mma.sync.aligned.m16n8k16.row.col.f32.f16.f16.f32 "                   \
        "{%0,%1,%2,%3}, {%4,%5,%6,%7}, {%8,%9}, {%0,%1,%2,%3};"                \
        : "+f"(acc[0]), "+f"(acc[1]), "+f"(acc[2]), "+f"(acc[3])               \
        : "r"(a0), "r"(a1), "r"(a2), "r"(a3), "r"(b0), "r"(b1))

#define LDSM4(r, addr)                                                         \
    asm volatile("ldmatrix.sync.aligned.m8n8.x4.shared.b16 {%0,%1,%2,%3}, [%4];" \
        : "=r"((r)[0]), "=r"((r)[1]), "=r"((r)[2]), "=r"((r)[3]) : "r"(addr))

/* ======= fp16 m16n8k16 NT GEMM, cp.async 3-stage + ldmatrix =============== */
/* CTA 128x128, BK=32 halves, 512 thr = 16 warps, warp tile 32x32.            */
/* A,B pre-split to half hi/lo in GMEM. PREC3: hh+hl+lh; PREC3=0: hh only.    */
/* SMEM: rows of 32 halves (64B) at 80B pitch (LDSM conflict-free).           */
/* mode 0: C = acc ; 1: C += acc ; 2: C = softplus(acc + bias[n])             */
#define PQ      80u                        /* row pitch bytes */
#define TILE_B  (128 * PQ)                 /* 10240 B per tile */

template <int PREC3>
__global__ void __launch_bounds__(512)
hgemm_nt(const half* __restrict__ Ah, const half* __restrict__ Al, int lda,
         const half* __restrict__ Bh, const half* __restrict__ Bl, int ldb,
         float* __restrict__ C, int ldc, int N, int K, int mode,
         const float* __restrict__ bias) {
    extern __shared__ uint8_t smem[];
    constexpr uint32_t NTI = PREC3 ? 4 : 2;
    constexpr uint32_t STAGE_B = NTI * TILE_B;
    const uint32_t sb = smem_u32(smem);
    const int tid = threadIdx.x;
    const int wid = tid >> 5;
    const int lane = tid & 31;
    const int g = lane >> 2;
    const int t = lane & 3;
    const int m0 = blockIdx.y * 128;
    const int n0 = blockIdx.x * 128;
    const int wm = (wid & 3) * 32;
    const int wn = (wid >> 2) * 32;

    /* staging: each thread owns (row = tid/4, 16B chunk = tid%4) per tile */
    const int srow = tid >> 2;
    const int sch = tid & 3;
    int brow = n0 + srow; if (brow > N - 1) brow = N - 1;
    const half* aS  = Ah + (size_t)(m0 + srow) * lda + sch * 8;
    const half* alS = Al + (size_t)(m0 + srow) * lda + sch * 8;
    const half* bS  = Bh + (size_t)brow * ldb + sch * 8;
    const half* blS = Bl + (size_t)brow * ldb + sch * 8;
    const uint32_t sdst = (uint32_t)srow * PQ + sch * 16;

    /* ldmatrix per-lane offsets */
    const int sel = lane >> 3, rin = lane & 7;
    const uint32_t a_loff = (uint32_t)(rin + 8 * (sel & 1)) * PQ + (uint32_t)(sel >> 1) * 16;
    const uint32_t b_loff = (uint32_t)(rin + 8 * (sel >> 1)) * PQ + (uint32_t)(sel & 1) * 16;

    float acc[2][4][4];
#pragma unroll
    for (int mi = 0; mi < 2; mi++)
#pragma unroll
        for (int ni = 0; ni < 4; ni++)
#pragma unroll
            for (int q = 0; q < 4; q++) acc[mi][ni][q] = 0.f;

    const int nk = K >> 5;   /* always >= 2 here */

    auto load_stage = [&](int slot, int kt) {
        const uint32_t base = sb + (uint32_t)slot * STAGE_B + sdst;
        const int ko = kt * 32;
        cp16(base, aS + ko);
        if (PREC3) cp16(base + TILE_B, alS + ko);
        cp16(base + (PREC3 ? 2 : 1) * TILE_B, bS + ko);
        if (PREC3) cp16(base + 3 * TILE_B, blS + ko);
    };

    load_stage(0, 0);
    asm volatile("cp.async.commit_group;" ::: "memory");
    load_stage(1, 1);
    asm volatile("cp.async.commit_group;" ::: "memory");

    for (int kt = 0; kt < nk; kt++) {
        asm volatile("cp.async.wait_group 1;" ::: "memory");
        __syncthreads();
        if (kt + 2 < nk) load_stage((kt + 2) % 3, kt + 2);
        asm volatile("cp.async.commit_group;" ::: "memory");

        const uint32_t stA  = sb + (uint32_t)(kt % 3) * STAGE_B;
        const uint32_t stAl = stA + TILE_B;
        const uint32_t stB  = stA + (PREC3 ? 2 : 1) * TILE_B;
        const uint32_t stBl = stB + TILE_B;

#pragma unroll
        for (int ks = 0; ks < 2; ks++) {
            const uint32_t ko = ks * 32;   /* 16 halves = 32B */
            uint32_t ah[2][4], bh[2][4];
            LDSM4(ah[0], stA + (wm + 0)  * PQ + ko + a_loff);
            LDSM4(ah[1], stA + (wm + 16) * PQ + ko + a_loff);
            LDSM4(bh[0], stB + (wn + 0)  * PQ + ko + b_loff);
            LDSM4(bh[1], stB + (wn + 16) * PQ + ko + b_loff);
            if (PREC3) {
                uint32_t al[2][4], bl[2][4];
                LDSM4(al[0], stAl + (wm + 0)  * PQ + ko + a_loff);
                LDSM4(al[1], stAl + (wm + 16) * PQ + ko + a_loff);
                LDSM4(bl[0], stBl + (wn + 0)  * PQ + ko + b_loff);
                LDSM4(bl[1], stBl + (wn + 16) * PQ + ko + b_loff);
                /* hi x lo */
#pragma unroll
                for (int mi = 0; mi < 2; mi++)
#pragma unroll
                    for (int nj = 0; nj < 2; nj++) {
                        MMA_F16(acc[mi][nj * 2 + 0], ah[mi][0], ah[mi][1],
                                ah[mi][2], ah[mi][3], bl[nj][0], bl[nj][1]);
                        MMA_F16(acc[mi][nj * 2 + 1], ah[mi][0], ah[mi][1],
                                ah[mi][2], ah[mi][3], bl[nj][2], bl[nj][3]);
                    }
                /* lo x hi */
#pragma unroll
                for (int mi = 0; mi < 2; mi++)
#pragma unroll
                    for (int nj = 0; nj < 2; nj++) {
                        MMA_F16(acc[mi][nj * 2 + 0], al[mi][0], al[mi][1],
                                al[mi][2], al[mi][3], bh[nj][0], bh[nj][1]);
                        MMA_F16(acc[mi][nj * 2 + 1], al[mi][0], al[mi][1],
                                al[mi][2], al[mi][3], bh[nj][2], bh[nj][3]);
                    }
            }
            /* hi x hi */
#pragma unroll
            for (int mi = 0; mi < 2; mi++)
#pragma unroll
                for (int nj = 0; nj < 2; nj++) {
                    MMA_F16(acc[mi][nj * 2 + 0], ah[mi][0], ah[mi][1],
                            ah[mi][2], ah[mi][3], bh[nj][0], bh[nj][1]);
                    MMA_F16(acc[mi][nj * 2 + 1], ah[mi][0], ah[mi][1],
                            ah[mi][2], ah[mi][3], bh[nj][2], bh[nj][3]);
                }
        }
    }

    /* ---- epilogue: c0,c1 -> (row g, cols 2t,2t+1); c2,c3 -> row g+8 ------ */
    /* float2 only when (m*ldc + n) even: ldc may be ODD (VOCAB=50257).       */
#pragma unroll
    for (int mi = 0; mi < 2; mi++) {
#pragma unroll
        for (int ni = 0; ni < 4; ni++) {
            const int m = m0 + wm + mi * 16 + g;
            const int n = n0 + wn + ni * 8 + t * 2;
            if (n < N) {
                float v0x = acc[mi][ni][0], v0y = acc[mi][ni][1];
                float v1x = acc[mi][ni][2], v1y = acc[mi][ni][3];
                float* p0 = C + (size_t)m * ldc + n;
                float* p1 = C + (size_t)(m + 8) * ldc + n;
                const bool al2 = ((((size_t)m * (size_t)ldc + (size_t)n) & 1) == 0);
                if (n + 1 < N) {
                    if (al2) {
                        float2 v0 = make_float2(v0x, v0y);
                        float2 v1 = make_float2(v1x, v1y);
                        if (mode == 1) {
                            float2 o0 = *(float2*)p0, o1 = *(float2*)p1;
                            v0.x += o0.x; v0.y += o0.y; v1.x += o1.x; v1.y += o1.y;
                        } else if (mode == 2) {
                            float b0 = bias[n], b1 = bias[n + 1];
                            v0.x = softplus_f(v0.x + b0); v0.y = softplus_f(v0.y + b1);
                            v1.x = softplus_f(v1.x + b0); v1.y = softplus_f(v1.y + b1);
                        }
                        *(float2*)p0 = v0;
                        *(float2*)p1 = v1;
                    } else {
                        if (mode == 1) {
                            v0x += p0[0]; v0y += p0[1];
                            v1x += p1[0]; v1y += p1[1];
                        } else if (mode == 2) {
                            float b0 = bias[n], b1 = bias[n + 1];
                            v0x = softplus_f(v0x + b0); v0y = softplus_f(v0y + b1);
                            v1x = softplus_f(v1x + b0); v1y = softplus_f(v1y + b1);
                        }
                        p0[0] = v0x; p0[1] = v0y;
                        p1[0] = v1x; p1[1] = v1y;
                    }
                } else {
                    if (mode == 1) { v0x += *p0; v1x += *p1; }
                    else if (mode == 2) {
                        float b0 = bias[n];
                        v0x = softplus_f(v0x + b0); v1x = softplus_f(v1x + b0);
                    }
                    *p0 = v0x;
                    *p1 = v1x;
                }
            }
        }
    }
}

/* ---------------- fp32 -> fp16 hi/lo split -------------------------------- */
__global__ void split_kernel(const float* __restrict__ src,
                             half* __restrict__ hi, half* __restrict__ lo,
                             int n4) {
    int i = blockIdx.x * blockDim.x + threadIdx.x;
    if (i < n4) {
        float4 v = ((const float4*)src)[i];
        half2 h0 = __floats2half2_rn(v.x, v.y);
        half2 h1 = __floats2half2_rn(v.z, v.w);
        ((half2*)hi)[i * 2 + 0] = h0;
        ((half2*)hi)[i * 2 + 1] = h1;
        half2 l0 = __floats2half2_rn(v.x - __low2float(h0), v.y - __high2float(h0));
        half2 l1 = __floats2half2_rn(v.z - __low2float(h1), v.w - __high2float(h1));
        ((half2*)lo)[i * 2 + 0] = l0;
        ((half2*)lo)[i * 2 + 1] = l1;
    }
}
__global__ void cvt_kernel(const float* __restrict__ src,
                           half* __restrict__ hi, int n4) {
    int i = blockIdx.x * blockDim.x + threadIdx.x;
    if (i < n4) {
        float4 v = ((const float4*)src)[i];
        ((half2*)hi)[i * 2 + 0] = __floats2half2_rn(v.x, v.y);
        ((half2*)hi)[i * 2 + 1] = __floats2half2_rn(v.z, v.w);
    }
}

/* ---------------- embedding gather --------------------------------------- */
__global__ void embed_kernel(const int* __restrict__ tok,
                             const float* __restrict__ W,
                             float* __restrict__ x) {
    int row = blockIdx.x;
    int t = tok[row];
    const float4* src = (const float4*)(W + (size_t)t * N_EMBD);
    float4* dst = (float4*)(x + (size_t)row * N_EMBD);
    dst[threadIdx.x] = src[threadIdx.x];
}

/* ---------------- rmsnorm ------------------------------------------------- */
__global__ void rmsnorm_kernel(const float* __restrict__ x,
                               const float* __restrict__ w,
                               const float* __restrict__ b,
                               float* __restrict__ out) {
    int row = blockIdx.x;
    const float4* xv = (const float4*)(x + (size_t)row * N_EMBD);
    float4 v = xv[threadIdx.x];
    float ss = v.x * v.x + v.y * v.y + v.z * v.z + v.w * v.w;
#pragma unroll
    for (int o = 16; o; o >>= 1) ss += __shfl_xor_sync(0xffffffffu, ss, o);
    __shared__ float red[8];
    if ((threadIdx.x & 31) == 0) red[threadIdx.x >> 5] = ss;
    __syncthreads();
    float tot = 0.f;
#pragma unroll
    for (int i = 0; i < 8; i++) tot += red[i];
    float inv = rsqrtf(tot * (1.f / N_EMBD) + 1e-6f);
    const float4* wv = (const float4*)w;
    const float4* bv = (const float4*)b;
    float4 ww = wv[threadIdx.x], bb = bv[threadIdx.x];
    float4 o4;
    o4.x = v.x * inv * ww.x + bb.x;
    o4.y = v.y * inv * ww.y + bb.y;
    o4.z = v.z * inv * ww.z + bb.z;
    o4.w = v.w * inv * ww.w + bb.w;
    ((float4*)(out + (size_t)row * N_EMBD))[threadIdx.x] = o4;
}

/* ---------------- depthwise causal conv (width 4) + silu ----------------- */
__global__ void conv_silu_kernel(const float* __restrict__ xr,
                                 const float* __restrict__ cw,
                                 const float* __restrict__ cb,
                                 float* __restrict__ xc) {
    int idx = blockIdx.x * blockDim.x + threadIdx.x;
    int t = idx >> 11;
    int d = idx & (D_INNER - 1);
    const float* w = cw + d * 4;
    float acc = cb[d];
#pragma unroll
    for (int j = 0; j < 4; j++) {
        int ti = t - 3 + j;
        float xv = (ti >= 0) ? xr[(size_t)ti * (2 * D_INNER) + d] : 0.f;
        acc += xv * w[j];
    }
    xc[idx] = silu_f(acc);
}

/* ---------------- selective scan ------------------------------------------ */
__global__ void scan_kernel(const float* __restrict__ xdbl,
                            const float* __restrict__ delta,
                            const float* __restrict__ xc,
                            const float* __restrict__ xr,
                            const float* __restrict__ A_log,
                            const float* __restrict__ Dp,
                            float* __restrict__ y) {
    int lane = threadIdx.x & 15;
    int ch = blockIdx.x * (blockDim.x >> 4) + (threadIdx.x >> 4);
    float Aval = -__expf(A_log[ch * D_STATE + lane]);
    float Dv = Dp[ch];
    float s = 0.f;
    for (int t = 0; t < L_SEQ; t++) {
        float dt = delta[(size_t)t * D_INNER + ch];
        float ut = xc[(size_t)t * D_INNER + ch];
        float Bt = xdbl[(size_t)t * XDBL + DT_RANK + lane];
        float Ct = xdbl[(size_t)t * XDBL + DT_RANK + D_STATE + lane];
        s = __expf(dt * Aval) * s + (dt * Bt) * ut;
        float v = s * Ct;
        v += __shfl_xor_sync(0xffffffffu, v, 8);
        v += __shfl_xor_sync(0xffffffffu, v, 4);
        v += __shfl_xor_sync(0xffffffffu, v, 2);
        v += __shfl_xor_sync(0xffffffffu, v, 1);
        if (lane == 0) {
            float r = xr[(size_t)t * (2 * D_INNER) + D_INNER + ch];
            y[(size_t)t * D_INNER + ch] = (v + ut * Dv) * silu_f(r);
        }
    }
}

/* ---------------- launcher ------------------------------------------------ */
#define SMEM_P3 (3 * 4 * TILE_B)   /* 122880 B */
#define SMEM_P1 (3 * 2 * TILE_B)   /* 61440 B  */

static void split_arr(const float* src, half* hi, half* lo, size_t n) {
    int n4 = (int)(n / 4);
    split_kernel<<<(n4 + 255) / 256, 256>>>(src, hi, lo, n4);
}

extern "C" void kernel_launch(void* const* d_in, const int* in_sizes, int n_in,
                              void* d_out, int out_size) {
    const int*   tokens   = (const int*)  d_in[0];
    const float* emb_W    = (const float*)d_in[1];
    const float* in_projW = (const float*)d_in[2];
    const float* conv_W   = (const float*)d_in[3];
    const float* conv_b   = (const float*)d_in[4];
    const float* xproj_W  = (const float*)d_in[5];
    const float* dt_W     = (const float*)d_in[6];
    const float* dt_b     = (const float*)d_in[7];
    const float* A_log    = (const float*)d_in[8];
    const float* Dp       = (const float*)d_in[9];
    const float* out_W    = (const float*)d_in[10];
    const float* rms_w    = (const float*)d_in[11];
    const float* rms_b    = (const float*)d_in[12];
    const float* normf_w  = (const float*)d_in[13];
    const float* normf_b  = (const float*)d_in[14];
    float* out = (float*)d_out;

    cudaFuncSetAttribute(hgemm_nt<1>, cudaFuncAttributeMaxDynamicSharedMemorySize,
                         SMEM_P3);
    cudaFuncSetAttribute(hgemm_nt<0>, cudaFuncAttributeMaxDynamicSharedMemorySize,
                         SMEM_P1);

    float *x, *h, *xr, *xc, *xdbl, *delta, *y;
    cudaGetSymbolAddress((void**)&x,     g_x);
    cudaGetSymbolAddress((void**)&h,     g_h);
    cudaGetSymbolAddress((void**)&xr,    g_xr);
    cudaGetSymbolAddress((void**)&xc,    g_xc);
    cudaGetSymbolAddress((void**)&xdbl,  g_xdbl);
    cudaGetSymbolAddress((void**)&delta, g_delta);
    cudaGetSymbolAddress((void**)&y,     g_y);

    half *h_hi, *h_lo, *xc_hi, *xc_lo, *xd_hi, *xd_lo, *y_hi, *y_lo;
    half *win_hi, *win_lo, *wxp_hi, *wxp_lo, *wdt_hi, *wdt_lo, *wout_hi, *wout_lo, *emb_hi;
    cudaGetSymbolAddress((void**)&h_hi,   g_h_hi);
    cudaGetSymbolAddress((void**)&h_lo,   g_h_lo);
    cudaGetSymbolAddress((void**)&xc_hi,  g_xc_hi);
    cudaGetSymbolAddress((void**)&xc_lo,  g_xc_lo);
    cudaGetSymbolAddress((void**)&xd_hi,  g_xdbl_hi);
    cudaGetSymbolAddress((void**)&xd_lo,  g_xdbl_lo);
    cudaGetSymbolAddress((void**)&y_hi,   g_y_hi);
    cudaGetSymbolAddress((void**)&y_lo,   g_y_lo);
    cudaGetSymbolAddress((void**)&win_hi, g_win_hi);
    cudaGetSymbolAddress((void**)&win_lo, g_win_lo);
    cudaGetSymbolAddress((void**)&wxp_hi, g_wxp_hi);
    cudaGetSymbolAddress((void**)&wxp_lo, g_wxp_lo);
    cudaGetSymbolAddress((void**)&wdt_hi, g_wdt_hi);
    cudaGetSymbolAddress((void**)&wdt_lo, g_wdt_lo);
    cudaGetSymbolAddress((void**)&wout_hi, g_wout_hi);
    cudaGetSymbolAddress((void**)&wout_lo, g_wout_lo);
    cudaGetSymbolAddress((void**)&emb_hi, g_emb_hi);

    /* weight splits (once per launch) */
    split_arr(in_projW, win_hi, win_lo, (size_t)N_LAYERS * 2 * D_INNER * N_EMBD);
    split_arr(xproj_W,  wxp_hi, wxp_lo, (size_t)N_LAYERS * XDBL * D_INNER);
    split_arr(dt_W,     wdt_hi, wdt_lo, (size_t)N_LAYERS * D_INNER * DT_RANK);
    split_arr(out_W,    wout_hi, wout_lo, (size_t)N_LAYERS * N_EMBD * D_INNER);
    {
        int n4 = (int)((size_t)VOCAB * N_EMBD / 4);
        cvt_kernel<<<(n4 + 255) / 256, 256>>>(emb_W, emb_hi, n4);
    }

    embed_kernel<<<L_SEQ, 256>>>(tokens, emb_W, x);

    for (int i = 0; i < N_LAYERS; i++) {
        rmsnorm_kernel<<<L_SEQ, 256>>>(x, rms_w + i * N_EMBD, rms_b + i * N_EMBD, h);
        split_arr(h, h_hi, h_lo, (size_t)L_SEQ * N_EMBD);
        /* xr = h @ in_proj_W^T  [2048 x 4096 x 1024] */
        hgemm_nt<1><<<dim3(2 * D_INNER / 128, 16), 512, SMEM_P3>>>(
            h_hi, h_lo, N_EMBD,
            win_hi + (size_t)i * 2 * D_INNER * N_EMBD,
            win_lo + (size_t)i * 2 * D_INNER * N_EMBD, N_EMBD,
            xr, 2 * D_INNER, 2 * D_INNER, N_EMBD, 0, nullptr);
        conv_silu_kernel<<<L_SEQ * D_INNER / 256, 256>>>(
            xr, conv_W + (size_t)i * D_INNER * D_CONV, conv_b + i * D_INNER, xc);
        split_arr(xc, xc_hi, xc_lo, (size_t)L_SEQ * D_INNER);
        /* x_dbl = xc @ xproj_W^T  [2048 x 96 x 2048] */
        hgemm_nt<1><<<dim3(1, 16), 512, SMEM_P3>>>(
            xc_hi, xc_lo, D_INNER,
            wxp_hi + (size_t)i * XDBL * D_INNER,
            wxp_lo + (size_t)i * XDBL * D_INNER, D_INNER,
            xdbl, XDBL, XDBL, D_INNER, 0, nullptr);
        split_arr(xdbl, xd_hi, xd_lo, (size_t)L_SEQ * XDBL);
        /* delta = softplus(x_dbl[:, :64] @ dt_W^T + dt_b)  [2048 x 2048 x 64] */
        hgemm_nt<1><<<dim3(D_INNER / 128, 16), 512, SMEM_P3>>>(
            xd_hi, xd_lo, XDBL,
            wdt_hi + (size_t)i * D_INNER * DT_RANK,
            wdt_lo + (size_t)i * D_INNER * DT_RANK, DT_RANK,
            delta, D_INNER, D_INNER, DT_RANK, 2, dt_b + i * D_INNER);
        scan_kernel<<<D_INNER / 8, 128>>>(
            xdbl, delta, xc, xr,
            A_log + (size_t)i * D_INNER * D_STATE, Dp + i * D_INNER, y);
        split_arr(y, y_hi, y_lo, (size_t)L_SEQ * D_INNER);
        /* x += y @ out_W^T  [2048 x 1024 x 2048] */
        hgemm_nt<1><<<dim3(N_EMBD / 128, 16), 512, SMEM_P3>>>(
            y_hi, y_lo, D_INNER,
            wout_hi + (size_t)i * N_EMBD * D_INNER,
            wout_lo + (size_t)i * N_EMBD * D_INNER, D_INNER,
            x, N_EMBD, N_EMBD, D_INNER, 1, nullptr);
    }

    rmsnorm_kernel<<<L_SEQ, 256>>>(x, normf_w, normf_b, h);
    {
        int n4 = (int)((size_t)L_SEQ * N_EMBD / 4);
        cvt_kernel<<<(n4 + 255) / 256, 256>>>(h, h_hi, n4);
    }
    /* tied LM head (single-pass fp16): out = h @ emb_W^T  [2048 x 50257 x 1024] */
    hgemm_nt<0><<<dim3((VOCAB + 127) / 128, 16), 512, SMEM_P1>>>(
        h_hi, h_hi, N_EMBD, emb_hi, emb_hi, N_EMBD,
        out, VOCAB, VOCAB, N_EMBD, 0, nullptr);
}